// round 3
// baseline (speedup 1.0000x reference)
#include <cuda_runtime.h>
#include <math.h>

#define NV 262144
#define NE 786432
#define CIMG 256
#define HID 128
#define HWD 64
#define DIN 131
#define BM 64

// scratch (static device globals; no runtime allocation allowed)
__device__ float g_y[(size_t)NV * HID];   // y accumulator / current activations
__device__ float g_z[(size_t)NV * HID];   // z (message) features

// ---------------------------------------------------------------------------
// Kernel 1: fused bilinear vert_align + bottleneck GEMM + bias + ReLU -> g_y
// grid = NV/BM blocks, 256 threads. Each block: 64 verts x 128 outputs.
// ---------------------------------------------------------------------------
__global__ void __launch_bounds__(256)
k_bottleneck(const float* __restrict__ x, const float* __restrict__ verts,
             const float* __restrict__ bw, const float* __restrict__ bb)
{
    extern __shared__ float sm[];
    float* As  = sm;                      // [BM][260]  (stride 260: %32==4 -> conflict-free)
    float* Ws  = As + BM * 260;           // [32][128]
    int*   sIdx = (int*)(Ws + 32 * 128);  // [BM][4]
    float* sW   = (float*)(sIdx + BM * 4);// [BM][4]

    const int tid = threadIdx.x;
    const int v0  = blockIdx.x * BM;

    // per-vertex bilinear params (grid_sample, border padding, align_corners)
    if (tid < BM) {
        int v = v0 + tid;
        float px = (verts[v * 3 + 0] + 1.0f) * 0.5f * (float)(HWD - 1);
        float py = (verts[v * 3 + 1] + 1.0f) * 0.5f * (float)(HWD - 1);
        float x0f = floorf(px), y0f = floorf(py);
        float wx = px - x0f, wy = py - y0f;
        int x0 = (int)x0f; x0 = x0 < 0 ? 0 : (x0 > HWD - 1 ? HWD - 1 : x0);
        int x1 = x0 + 1 > HWD - 1 ? HWD - 1 : x0 + 1;
        int y0 = (int)y0f; y0 = y0 < 0 ? 0 : (y0 > HWD - 1 ? HWD - 1 : y0);
        int y1 = y0 + 1 > HWD - 1 ? HWD - 1 : y0 + 1;
        sIdx[tid * 4 + 0] = y0 * HWD + x0;
        sIdx[tid * 4 + 1] = y0 * HWD + x1;
        sIdx[tid * 4 + 2] = y1 * HWD + x0;
        sIdx[tid * 4 + 3] = y1 * HWD + x1;
        sW[tid * 4 + 0] = (1.0f - wx) * (1.0f - wy);
        sW[tid * 4 + 1] = wx * (1.0f - wy);
        sW[tid * 4 + 2] = (1.0f - wx) * wy;
        sW[tid * 4 + 3] = wx * wy;
    }
    __syncthreads();

    // build A tile: As[m][c] = bilinear sample of channel c at vertex m
    {
        const int c = tid;  // one channel per thread (256 threads == 256 channels)
        const float* im = x + c * (HWD * HWD);
        #pragma unroll 4
        for (int m = 0; m < BM; m++) {
            float val = sW[m * 4 + 0] * im[sIdx[m * 4 + 0]]
                      + sW[m * 4 + 1] * im[sIdx[m * 4 + 1]]
                      + sW[m * 4 + 2] * im[sIdx[m * 4 + 2]]
                      + sW[m * 4 + 3] * im[sIdx[m * 4 + 3]];
            As[m * 260 + c] = val;
        }
    }

    const int m0 = tid & 7;
    const int n0 = (tid >> 3) << 2;
    float4 bias = *(const float4*)(bb + n0);
    float acc[8][4];
    #pragma unroll
    for (int i = 0; i < 8; i++) {
        acc[i][0] = bias.x; acc[i][1] = bias.y; acc[i][2] = bias.z; acc[i][3] = bias.w;
    }

    for (int kc = 0; kc < CIMG; kc += 32) {
        __syncthreads();
        #pragma unroll
        for (int t = 0; t < 4; t++)
            ((float4*)Ws)[t * 256 + tid] = ((const float4*)(bw + kc * HID))[t * 256 + tid];
        __syncthreads();
        #pragma unroll
        for (int kk = 0; kk < 32; kk++) {
            float4 b = *(const float4*)(Ws + kk * HID + n0);
            #pragma unroll
            for (int i = 0; i < 8; i++) {
                float a = As[(m0 + 8 * i) * 260 + kc + kk];
                acc[i][0] = fmaf(a, b.x, acc[i][0]);
                acc[i][1] = fmaf(a, b.y, acc[i][1]);
                acc[i][2] = fmaf(a, b.z, acc[i][2]);
                acc[i][3] = fmaf(a, b.w, acc[i][3]);
            }
        }
    }
    #pragma unroll
    for (int i = 0; i < 8; i++) {
        int v = v0 + m0 + 8 * i;
        float4 o;
        o.x = fmaxf(acc[i][0], 0.0f);
        o.y = fmaxf(acc[i][1], 0.0f);
        o.z = fmaxf(acc[i][2], 0.0f);
        o.w = fmaxf(acc[i][3], 0.0f);
        *(float4*)(g_y + (size_t)v * HID + n0) = o;
    }
}

// ---------------------------------------------------------------------------
// Kernel 2: one GCN layer GEMM pair.
//   A = [relu(g_y), verts]  (64 x 131 tile in smem; read BEFORE writes -> in-place safe)
//   g_y <- A @ w0 + b0   (y, pre-scatter)
//   g_z <- A @ w1 + b1
// ---------------------------------------------------------------------------
__global__ void __launch_bounds__(256)
k_layer(const float* __restrict__ verts,
        const float* __restrict__ w0, const float* __restrict__ b0,
        const float* __restrict__ w1, const float* __restrict__ b1)
{
    extern __shared__ float sm[];
    float* As  = sm;               // [BM][132]  (stride 132: %32==4 -> conflict-free)
    float* Ws0 = As + BM * 132;    // [32][128]
    float* Ws1 = Ws0 + 32 * 128;   // [32][128]

    const int tid = threadIdx.x;
    const int v0  = blockIdx.x * BM;

    // A tile: relu'd activations (float4 coalesced) + vertex coords
    for (int idx = tid; idx < BM * 32; idx += 256) {
        int m = idx >> 5, c4 = idx & 31;
        float4 f = *(const float4*)(g_y + (size_t)(v0 + m) * HID + c4 * 4);
        f.x = fmaxf(f.x, 0.0f); f.y = fmaxf(f.y, 0.0f);
        f.z = fmaxf(f.z, 0.0f); f.w = fmaxf(f.w, 0.0f);
        *(float4*)(As + m * 132 + c4 * 4) = f;
    }
    if (tid < BM) {
        int v = v0 + tid;
        As[tid * 132 + 128] = verts[v * 3 + 0];
        As[tid * 132 + 129] = verts[v * 3 + 1];
        As[tid * 132 + 130] = verts[v * 3 + 2];
    }

    const int m0 = tid & 7;
    const int n0 = (tid >> 3) << 2;
    float4 by = *(const float4*)(b0 + n0);
    float4 bz = *(const float4*)(b1 + n0);
    float accY[8][4], accZ[8][4];
    #pragma unroll
    for (int i = 0; i < 8; i++) {
        accY[i][0] = by.x; accY[i][1] = by.y; accY[i][2] = by.z; accY[i][3] = by.w;
        accZ[i][0] = bz.x; accZ[i][1] = bz.y; accZ[i][2] = bz.z; accZ[i][3] = bz.w;
    }

    for (int kc = 0; kc < 128; kc += 32) {
        __syncthreads();
        #pragma unroll
        for (int t = 0; t < 4; t++) {
            ((float4*)Ws0)[t * 256 + tid] = ((const float4*)(w0 + kc * HID))[t * 256 + tid];
            ((float4*)Ws1)[t * 256 + tid] = ((const float4*)(w1 + kc * HID))[t * 256 + tid];
        }
        __syncthreads();
        #pragma unroll
        for (int kk = 0; kk < 32; kk++) {
            float4 wy = *(const float4*)(Ws0 + kk * HID + n0);
            float4 wz = *(const float4*)(Ws1 + kk * HID + n0);
            #pragma unroll
            for (int i = 0; i < 8; i++) {
                float a = As[(m0 + 8 * i) * 132 + kc + kk];
                accY[i][0] = fmaf(a, wy.x, accY[i][0]);
                accY[i][1] = fmaf(a, wy.y, accY[i][1]);
                accY[i][2] = fmaf(a, wy.z, accY[i][2]);
                accY[i][3] = fmaf(a, wy.w, accY[i][3]);
                accZ[i][0] = fmaf(a, wz.x, accZ[i][0]);
                accZ[i][1] = fmaf(a, wz.y, accZ[i][1]);
                accZ[i][2] = fmaf(a, wz.z, accZ[i][2]);
                accZ[i][3] = fmaf(a, wz.w, accZ[i][3]);
            }
        }
    }
    // tail: k = 128..130 (vertex-coordinate rows of the weight matrices)
    __syncthreads();
    if (tid < 96) {
        ((float4*)Ws0)[tid] = ((const float4*)(w0 + 128 * HID))[tid];
        ((float4*)Ws1)[tid] = ((const float4*)(w1 + 128 * HID))[tid];
    }
    __syncthreads();
    #pragma unroll
    for (int kk = 0; kk < 3; kk++) {
        float4 wy = *(const float4*)(Ws0 + kk * HID + n0);
        float4 wz = *(const float4*)(Ws1 + kk * HID + n0);
        #pragma unroll
        for (int i = 0; i < 8; i++) {
            float a = As[(m0 + 8 * i) * 132 + 128 + kk];
            accY[i][0] = fmaf(a, wy.x, accY[i][0]);
            accY[i][1] = fmaf(a, wy.y, accY[i][1]);
            accY[i][2] = fmaf(a, wy.z, accY[i][2]);
            accY[i][3] = fmaf(a, wy.w, accY[i][3]);
            accZ[i][0] = fmaf(a, wz.x, accZ[i][0]);
            accZ[i][1] = fmaf(a, wz.y, accZ[i][1]);
            accZ[i][2] = fmaf(a, wz.z, accZ[i][2]);
            accZ[i][3] = fmaf(a, wz.w, accZ[i][3]);
        }
    }
    #pragma unroll
    for (int i = 0; i < 8; i++) {
        int v = v0 + m0 + 8 * i;
        *(float4*)(g_y + (size_t)v * HID + n0) =
            make_float4(accY[i][0], accY[i][1], accY[i][2], accY[i][3]);
        *(float4*)(g_z + (size_t)v * HID + n0) =
            make_float4(accZ[i][0], accZ[i][1], accZ[i][2], accZ[i][3]);
    }
}

// ---------------------------------------------------------------------------
// Kernel 3: symmetric edge scatter. One warp per edge; lane handles 4 channels.
//   g_y[e0] += g_z[e1];  g_y[e1] += g_z[e0];  (atomic)
// ---------------------------------------------------------------------------
__global__ void __launch_bounds__(256)
k_scatter(const int* __restrict__ edges)
{
    int gt = blockIdx.x * blockDim.x + threadIdx.x;
    int e = gt >> 5;
    int lane = gt & 31;
    if (e >= NE) return;
    int e0 = __ldg(edges + 2 * e);
    int e1 = __ldg(edges + 2 * e + 1);
    float4 a = *(const float4*)(g_z + (size_t)e1 * HID + lane * 4);
    float4 b = *(const float4*)(g_z + (size_t)e0 * HID + lane * 4);
    float* y0 = g_y + (size_t)e0 * HID + lane * 4;
    float* y1 = g_y + (size_t)e1 * HID + lane * 4;
    atomicAdd(y0 + 0, a.x); atomicAdd(y0 + 1, a.y);
    atomicAdd(y0 + 2, a.z); atomicAdd(y0 + 3, a.w);
    atomicAdd(y1 + 0, b.x); atomicAdd(y1 + 1, b.y);
    atomicAdd(y1 + 2, b.z); atomicAdd(y1 + 3, b.w);
}

// ---------------------------------------------------------------------------
// Kernel 4: final head. One warp per vertex.
//   nopos = relu(g_y[v])  -> out[3V ...]
//   deform = tanh([nopos, verts] @ offset_w + offset_b);  new_verts = verts + deform
// ---------------------------------------------------------------------------
__global__ void __launch_bounds__(256)
k_final(const float* __restrict__ verts, const float* __restrict__ ow,
        const float* __restrict__ ob, float* __restrict__ out)
{
    int gt = blockIdx.x * blockDim.x + threadIdx.x;
    int v = gt >> 5;
    int lane = gt & 31;
    if (v >= NV) return;

    float4 f = *(const float4*)(g_y + (size_t)v * HID + lane * 4);
    f.x = fmaxf(f.x, 0.0f); f.y = fmaxf(f.y, 0.0f);
    f.z = fmaxf(f.z, 0.0f); f.w = fmaxf(f.w, 0.0f);
    *(float4*)(out + (size_t)NV * 3 + (size_t)v * HID + lane * 4) = f;

    int k = lane * 4;
    float s0 = f.x * ow[k * 3 + 0] + f.y * ow[(k + 1) * 3 + 0]
             + f.z * ow[(k + 2) * 3 + 0] + f.w * ow[(k + 3) * 3 + 0];
    float s1 = f.x * ow[k * 3 + 1] + f.y * ow[(k + 1) * 3 + 1]
             + f.z * ow[(k + 2) * 3 + 1] + f.w * ow[(k + 3) * 3 + 1];
    float s2 = f.x * ow[k * 3 + 2] + f.y * ow[(k + 1) * 3 + 2]
             + f.z * ow[(k + 2) * 3 + 2] + f.w * ow[(k + 3) * 3 + 2];
    #pragma unroll
    for (int off = 16; off; off >>= 1) {
        s0 += __shfl_xor_sync(0xffffffffu, s0, off);
        s1 += __shfl_xor_sync(0xffffffffu, s1, off);
        s2 += __shfl_xor_sync(0xffffffffu, s2, off);
    }
    if (lane == 0) {
        float vx = verts[v * 3 + 0], vy = verts[v * 3 + 1], vz = verts[v * 3 + 2];
        s0 += vx * ow[384] + vy * ow[387] + vz * ow[390] + ob[0];
        s1 += vx * ow[385] + vy * ow[388] + vz * ow[391] + ob[1];
        s2 += vx * ow[386] + vy * ow[389] + vz * ow[392] + ob[2];
        out[v * 3 + 0] = vx + tanhf(s0);
        out[v * 3 + 1] = vy + tanhf(s1);
        out[v * 3 + 2] = vz + tanhf(s2);
    }
}

// ---------------------------------------------------------------------------
extern "C" void kernel_launch(void* const* d_in, const int* in_sizes, int n_in,
                              void* d_out, int out_size)
{
    const float* x     = (const float*)d_in[0];
    const float* verts = (const float*)d_in[1];
    const int*   edges = (const int*)d_in[2];
    const float* bw    = (const float*)d_in[3];
    const float* bb    = (const float*)d_in[4];
    const float* w0    = (const float*)d_in[5];
    const float* b0    = (const float*)d_in[6];
    const float* w1    = (const float*)d_in[7];
    const float* b1    = (const float*)d_in[8];
    const float* ow    = (const float*)d_in[9];
    const float* ob    = (const float*)d_in[10];
    float* out = (float*)d_out;

    const int SMEM_BN = (BM * 260 + 32 * HID) * 4 + BM * 4 * 4 * 2;   // ~85 KB
    const int SMEM_LY = (BM * 132 + 2 * 32 * HID) * 4;                // ~65 KB
    cudaFuncSetAttribute(k_bottleneck, cudaFuncAttributeMaxDynamicSharedMemorySize, SMEM_BN);
    cudaFuncSetAttribute(k_layer,      cudaFuncAttributeMaxDynamicSharedMemorySize, SMEM_LY);

    const int gemm_blocks = NV / BM;           // 4096
    k_bottleneck<<<gemm_blocks, 256, SMEM_BN>>>(x, verts, bw, bb);

    const int scat_blocks = (NE * 32) / 256;   // 98304
    for (int i = 0; i < 3; i++) {
        k_layer<<<gemm_blocks, 256, SMEM_LY>>>(verts,
                                               w0 + (size_t)i * DIN * HID, b0 + (size_t)i * HID,
                                               w1 + (size_t)i * DIN * HID, b1 + (size_t)i * HID);
        k_scatter<<<scat_blocks, 256>>>(edges);
    }

    const int fin_blocks = (NV * 32) / 256;    // 32768
    k_final<<<fin_blocks, 256>>>(verts, ow, ob, out);
}

// round 4
// speedup vs baseline: 1.2564x; 1.2564x over previous
#include <cuda_runtime.h>
#include <math.h>

#define NV 262144
#define NE 786432
#define CIMG 256
#define HID 128
#define HWD 64
#define DIN 131
#define BM 64

typedef unsigned long long u64;

// scratch (static device globals; no runtime allocation allowed)
__device__ float g_y[(size_t)NV * HID];   // y accumulator / current activations
__device__ float g_z[(size_t)NV * HID];   // z (message) features

static __device__ __forceinline__ unsigned smem_u32(const void* p) {
    return (unsigned)__cvta_generic_to_shared(p);
}
static __device__ __forceinline__ u64 pack2(float lo, float hi) {
    u64 r;
    asm("mov.b64 %0, {%1, %2};" : "=l"(r) : "f"(lo), "f"(hi));
    return r;
}
static __device__ __forceinline__ u64 pack_dup(float a) {
    u64 r;
    asm("mov.b64 %0, {%1, %1};" : "=l"(r) : "f"(a));
    return r;
}
static __device__ __forceinline__ void unpack2(u64 v, float& lo, float& hi) {
    asm("mov.b64 {%0, %1}, %2;" : "=f"(lo), "=f"(hi) : "l"(v));
}
#define FFMA2(acc, a, b) \
    asm("fma.rn.f32x2 %0, %1, %2, %0;" : "+l"(acc) : "l"(a), "l"(b))

#define LDS_V2B64(d0, d1, addr) \
    asm volatile("ld.shared.v2.b64 {%0, %1}, [%2];" : "=l"(d0), "=l"(d1) : "r"(addr))

// ---------------------------------------------------------------------------
// Kernel 1: fused bilinear vert_align + bottleneck GEMM + bias + ReLU -> g_y
// 512 threads. Each block: 64 verts x 128 outputs, K=256 (image channels).
// As stride 262 (%32==6 -> 16 distinct banks for m0=tid&15).
// ---------------------------------------------------------------------------
__global__ void __launch_bounds__(512)
k_bottleneck(const float* __restrict__ x, const float* __restrict__ verts,
             const float* __restrict__ bw, const float* __restrict__ bb)
{
    extern __shared__ float sm[];
    float* As   = sm;                       // [BM][262]
    float* Ws   = As + BM * 262;            // [32][128]
    int*   sIdx = (int*)(Ws + 32 * 128);    // [BM][4]
    float* sW   = (float*)(sIdx + BM * 4);  // [BM][4]

    const int tid = threadIdx.x;
    const int v0  = blockIdx.x * BM;

    if (tid < BM) {
        int v = v0 + tid;
        float px = (verts[v * 3 + 0] + 1.0f) * 0.5f * (float)(HWD - 1);
        float py = (verts[v * 3 + 1] + 1.0f) * 0.5f * (float)(HWD - 1);
        float x0f = floorf(px), y0f = floorf(py);
        float wx = px - x0f, wy = py - y0f;
        int x0 = (int)x0f; x0 = x0 < 0 ? 0 : (x0 > HWD - 1 ? HWD - 1 : x0);
        int x1 = x0 + 1 > HWD - 1 ? HWD - 1 : x0 + 1;
        int y0 = (int)y0f; y0 = y0 < 0 ? 0 : (y0 > HWD - 1 ? HWD - 1 : y0);
        int y1 = y0 + 1 > HWD - 1 ? HWD - 1 : y0 + 1;
        sIdx[tid * 4 + 0] = y0 * HWD + x0;
        sIdx[tid * 4 + 1] = y0 * HWD + x1;
        sIdx[tid * 4 + 2] = y1 * HWD + x0;
        sIdx[tid * 4 + 3] = y1 * HWD + x1;
        sW[tid * 4 + 0] = (1.0f - wx) * (1.0f - wy);
        sW[tid * 4 + 1] = wx * (1.0f - wy);
        sW[tid * 4 + 2] = (1.0f - wx) * wy;
        sW[tid * 4 + 3] = wx * wy;
    }
    __syncthreads();

    // A tile: 2 threads per channel, 32 verts each
    {
        const int c  = tid & 255;
        const int mh = (tid >> 8) * 32;
        const float* im = x + c * (HWD * HWD);
        #pragma unroll 4
        for (int mm = 0; mm < 32; mm++) {
            int m = mh + mm;
            float val = sW[m * 4 + 0] * im[sIdx[m * 4 + 0]]
                      + sW[m * 4 + 1] * im[sIdx[m * 4 + 1]]
                      + sW[m * 4 + 2] * im[sIdx[m * 4 + 2]]
                      + sW[m * 4 + 3] * im[sIdx[m * 4 + 3]];
            As[m * 262 + c] = val;
        }
    }

    const int m0 = tid & 15;
    const int n0 = (tid >> 4) << 2;
    const unsigned ws_b  = smem_u32(Ws) + n0 * 4;

    float4 bias = *(const float4*)(bb + n0);
    u64 acc[4][2];
    u64 b01 = pack2(bias.x, bias.y), b23 = pack2(bias.z, bias.w);
    #pragma unroll
    for (int i = 0; i < 4; i++) { acc[i][0] = b01; acc[i][1] = b23; }

    for (int kc = 0; kc < CIMG; kc += 32) {
        __syncthreads();
        #pragma unroll
        for (int t = 0; t < 2; t++)
            ((float4*)Ws)[t * 512 + tid] = ((const float4*)(bw + kc * HID))[t * 512 + tid];
        __syncthreads();
        #pragma unroll
        for (int kk = 0; kk < 32; kk++) {
            u64 w01, w23;
            LDS_V2B64(w01, w23, ws_b + (kk * HID) * 4);
            #pragma unroll
            for (int i = 0; i < 4; i++) {
                u64 a = pack_dup(As[(m0 + 16 * i) * 262 + kc + kk]);
                FFMA2(acc[i][0], a, w01);
                FFMA2(acc[i][1], a, w23);
            }
        }
    }
    #pragma unroll
    for (int i = 0; i < 4; i++) {
        int v = v0 + m0 + 16 * i;
        float f0, f1, f2, f3;
        unpack2(acc[i][0], f0, f1);
        unpack2(acc[i][1], f2, f3);
        *(float4*)(g_y + (size_t)v * HID + n0) =
            make_float4(fmaxf(f0, 0.f), fmaxf(f1, 0.f), fmaxf(f2, 0.f), fmaxf(f3, 0.f));
    }
}

// ---------------------------------------------------------------------------
// Kernel 2: one GCN layer GEMM pair (512 threads, packed f32x2 FMA).
//   A = [relu(g_y), verts]   (64 x 131 tile, smem stride 134)
//   g_y <- A @ w0 + b0 ;  g_z <- A @ w1 + b1
// ---------------------------------------------------------------------------
__global__ void __launch_bounds__(512)
k_layer(const float* __restrict__ verts,
        const float* __restrict__ w0, const float* __restrict__ b0,
        const float* __restrict__ w1, const float* __restrict__ b1)
{
    extern __shared__ float sm[];
    float* As  = sm;               // [BM][134]  (134 % 32 == 6 -> 16 distinct banks)
    float* Ws0 = As + BM * 134;    // [32][128]
    float* Ws1 = Ws0 + 32 * 128;   // [32][128]

    const int tid = threadIdx.x;
    const int v0  = blockIdx.x * BM;

    // A tile: relu'd activations + vertex coords
    for (int idx = tid; idx < BM * 32; idx += 512) {
        int m = idx >> 5, c4 = idx & 31;
        float4 f = *(const float4*)(g_y + (size_t)(v0 + m) * HID + c4 * 4);
        float* dst = As + m * 134 + c4 * 4;
        *(float2*)dst       = make_float2(fmaxf(f.x, 0.f), fmaxf(f.y, 0.f));
        *(float2*)(dst + 2) = make_float2(fmaxf(f.z, 0.f), fmaxf(f.w, 0.f));
    }
    if (tid < BM) {
        int v = v0 + tid;
        As[tid * 134 + 128] = verts[v * 3 + 0];
        As[tid * 134 + 129] = verts[v * 3 + 1];
        As[tid * 134 + 130] = verts[v * 3 + 2];
    }

    const int m0 = tid & 15;
    const int n0 = (tid >> 4) << 2;
    const unsigned ws0_b = smem_u32(Ws0) + n0 * 4;
    const unsigned ws1_b = smem_u32(Ws1) + n0 * 4;

    float4 by = *(const float4*)(b0 + n0);
    float4 bz = *(const float4*)(b1 + n0);
    u64 accY[4][2], accZ[4][2];
    {
        u64 y01 = pack2(by.x, by.y), y23 = pack2(by.z, by.w);
        u64 z01 = pack2(bz.x, bz.y), z23 = pack2(bz.z, bz.w);
        #pragma unroll
        for (int i = 0; i < 4; i++) {
            accY[i][0] = y01; accY[i][1] = y23;
            accZ[i][0] = z01; accZ[i][1] = z23;
        }
    }

    for (int kc = 0; kc < 128; kc += 32) {
        __syncthreads();
        #pragma unroll
        for (int t = 0; t < 2; t++) {
            ((float4*)Ws0)[t * 512 + tid] = ((const float4*)(w0 + kc * HID))[t * 512 + tid];
            ((float4*)Ws1)[t * 512 + tid] = ((const float4*)(w1 + kc * HID))[t * 512 + tid];
        }
        __syncthreads();
        #pragma unroll
        for (int kk = 0; kk < 32; kk++) {
            u64 wy01, wy23, wz01, wz23;
            LDS_V2B64(wy01, wy23, ws0_b + (kk * HID) * 4);
            LDS_V2B64(wz01, wz23, ws1_b + (kk * HID) * 4);
            #pragma unroll
            for (int i = 0; i < 4; i++) {
                u64 a = pack_dup(As[(m0 + 16 * i) * 134 + kc + kk]);
                FFMA2(accY[i][0], a, wy01);
                FFMA2(accY[i][1], a, wy23);
                FFMA2(accZ[i][0], a, wz01);
                FFMA2(accZ[i][1], a, wz23);
            }
        }
    }
    // tail: k = 128..130 (vertex-coordinate rows)
    __syncthreads();
    if (tid < 96) {
        ((float4*)Ws0)[tid] = ((const float4*)(w0 + 128 * HID))[tid];
        ((float4*)Ws1)[tid] = ((const float4*)(w1 + 128 * HID))[tid];
    }
    __syncthreads();
    #pragma unroll
    for (int kk = 0; kk < 3; kk++) {
        u64 wy01, wy23, wz01, wz23;
        LDS_V2B64(wy01, wy23, ws0_b + (kk * HID) * 4);
        LDS_V2B64(wz01, wz23, ws1_b + (kk * HID) * 4);
        #pragma unroll
        for (int i = 0; i < 4; i++) {
            u64 a = pack_dup(As[(m0 + 16 * i) * 134 + 128 + kk]);
            FFMA2(accY[i][0], a, wy01);
            FFMA2(accY[i][1], a, wy23);
            FFMA2(accZ[i][0], a, wz01);
            FFMA2(accZ[i][1], a, wz23);
        }
    }
    #pragma unroll
    for (int i = 0; i < 4; i++) {
        int v = v0 + m0 + 16 * i;
        float f0, f1, f2, f3;
        unpack2(accY[i][0], f0, f1);
        unpack2(accY[i][1], f2, f3);
        *(float4*)(g_y + (size_t)v * HID + n0) = make_float4(f0, f1, f2, f3);
        unpack2(accZ[i][0], f0, f1);
        unpack2(accZ[i][1], f2, f3);
        *(float4*)(g_z + (size_t)v * HID + n0) = make_float4(f0, f1, f2, f3);
    }
}

// ---------------------------------------------------------------------------
// Kernel 3: symmetric edge scatter. One warp per edge; lane handles 4 channels.
//   g_y[e0] += g_z[e1];  g_y[e1] += g_z[e0];  (vector RED, no return)
// ---------------------------------------------------------------------------
__global__ void __launch_bounds__(256)
k_scatter(const int* __restrict__ edges)
{
    int gt = blockIdx.x * blockDim.x + threadIdx.x;
    int e = gt >> 5;
    int lane = gt & 31;
    if (e >= NE) return;
    int e0 = __ldg(edges + 2 * e);
    int e1 = __ldg(edges + 2 * e + 1);
    float4 a = *(const float4*)(g_z + (size_t)e1 * HID + lane * 4);
    float4 b = *(const float4*)(g_z + (size_t)e0 * HID + lane * 4);
    float* y0 = g_y + (size_t)e0 * HID + lane * 4;
    float* y1 = g_y + (size_t)e1 * HID + lane * 4;
    asm volatile("red.global.add.v4.f32 [%0], {%1, %2, %3, %4};"
                 :: "l"(y0), "f"(a.x), "f"(a.y), "f"(a.z), "f"(a.w) : "memory");
    asm volatile("red.global.add.v4.f32 [%0], {%1, %2, %3, %4};"
                 :: "l"(y1), "f"(b.x), "f"(b.y), "f"(b.z), "f"(b.w) : "memory");
}

// ---------------------------------------------------------------------------
// Kernel 4: final head. One warp per vertex.
// ---------------------------------------------------------------------------
__global__ void __launch_bounds__(256)
k_final(const float* __restrict__ verts, const float* __restrict__ ow,
        const float* __restrict__ ob, float* __restrict__ out)
{
    int gt = blockIdx.x * blockDim.x + threadIdx.x;
    int v = gt >> 5;
    int lane = gt & 31;
    if (v >= NV) return;

    float4 f = *(const float4*)(g_y + (size_t)v * HID + lane * 4);
    f.x = fmaxf(f.x, 0.0f); f.y = fmaxf(f.y, 0.0f);
    f.z = fmaxf(f.z, 0.0f); f.w = fmaxf(f.w, 0.0f);
    *(float4*)(out + (size_t)NV * 3 + (size_t)v * HID + lane * 4) = f;

    int k = lane * 4;
    float s0 = f.x * ow[k * 3 + 0] + f.y * ow[(k + 1) * 3 + 0]
             + f.z * ow[(k + 2) * 3 + 0] + f.w * ow[(k + 3) * 3 + 0];
    float s1 = f.x * ow[k * 3 + 1] + f.y * ow[(k + 1) * 3 + 1]
             + f.z * ow[(k + 2) * 3 + 1] + f.w * ow[(k + 3) * 3 + 1];
    float s2 = f.x * ow[k * 3 + 2] + f.y * ow[(k + 1) * 3 + 2]
             + f.z * ow[(k + 2) * 3 + 2] + f.w * ow[(k + 3) * 3 + 2];
    #pragma unroll
    for (int off = 16; off; off >>= 1) {
        s0 += __shfl_xor_sync(0xffffffffu, s0, off);
        s1 += __shfl_xor_sync(0xffffffffu, s1, off);
        s2 += __shfl_xor_sync(0xffffffffu, s2, off);
    }
    if (lane == 0) {
        float vx = verts[v * 3 + 0], vy = verts[v * 3 + 1], vz = verts[v * 3 + 2];
        s0 += vx * ow[384] + vy * ow[387] + vz * ow[390] + ob[0];
        s1 += vx * ow[385] + vy * ow[388] + vz * ow[391] + ob[1];
        s2 += vx * ow[386] + vy * ow[389] + vz * ow[392] + ob[2];
        out[v * 3 + 0] = vx + tanhf(s0);
        out[v * 3 + 1] = vy + tanhf(s1);
        out[v * 3 + 2] = vz + tanhf(s2);
    }
}

// ---------------------------------------------------------------------------
extern "C" void kernel_launch(void* const* d_in, const int* in_sizes, int n_in,
                              void* d_out, int out_size)
{
    const float* x     = (const float*)d_in[0];
    const float* verts = (const float*)d_in[1];
    const int*   edges = (const int*)d_in[2];
    const float* bw    = (const float*)d_in[3];
    const float* bb    = (const float*)d_in[4];
    const float* w0    = (const float*)d_in[5];
    const float* b0    = (const float*)d_in[6];
    const float* w1    = (const float*)d_in[7];
    const float* b1    = (const float*)d_in[8];
    const float* ow    = (const float*)d_in[9];
    const float* ob    = (const float*)d_in[10];
    float* out = (float*)d_out;

    const int SMEM_BN = (BM * 262 + 32 * HID) * 4 + BM * 4 * 4 * 2;   // ~86 KB
    const int SMEM_LY = (BM * 134 + 2 * 32 * HID) * 4;                // ~66 KB
    cudaFuncSetAttribute(k_bottleneck, cudaFuncAttributeMaxDynamicSharedMemorySize, SMEM_BN);
    cudaFuncSetAttribute(k_layer,      cudaFuncAttributeMaxDynamicSharedMemorySize, SMEM_LY);

    const int gemm_blocks = NV / BM;           // 4096
    k_bottleneck<<<gemm_blocks, 512, SMEM_BN>>>(x, verts, bw, bb);

    const int scat_blocks = (NE * 32) / 256;   // 98304
    for (int i = 0; i < 3; i++) {
        k_layer<<<gemm_blocks, 512, SMEM_LY>>>(verts,
                                               w0 + (size_t)i * DIN * HID, b0 + (size_t)i * HID,
                                               w1 + (size_t)i * DIN * HID, b1 + (size_t)i * HID);
        k_scatter<<<scat_blocks, 256>>>(edges);
    }

    const int fin_blocks = (NV * 32) / 256;    // 32768
    k_final<<<fin_blocks, 256>>>(verts, ow, ob, out);
}

// round 7
// speedup vs baseline: 1.4525x; 1.1561x over previous
#include <cuda_runtime.h>
#include <math.h>

#define NV 262144
#define NE 786432
#define CIMG 256
#define HID 128
#define HWD 64
#define DIN 131
#define BM 64
#define NTILES (NV / BM)

typedef unsigned long long u64;

// scratch (static device globals; no runtime allocation allowed)
__device__ float g_y[(size_t)NV * HID];   // y accumulator / current activations
__device__ float g_z[(size_t)NV * HID];   // z (message) features
// CSR scratch
__device__ int g_deg[NV];
__device__ int g_off[NV];
__device__ int g_cur[NV];
__device__ int g_adj[2 * NE];
__device__ int g_bsum[256];

static __device__ __forceinline__ unsigned smem_u32(const void* p) {
    return (unsigned)__cvta_generic_to_shared(p);
}
static __device__ __forceinline__ u64 pack2(float lo, float hi) {
    u64 r;
    asm("mov.b64 %0, {%1, %2};" : "=l"(r) : "f"(lo), "f"(hi));
    return r;
}
static __device__ __forceinline__ u64 pack_dup(float a) {
    u64 r;
    asm("mov.b64 %0, {%1, %1};" : "=l"(r) : "f"(a));
    return r;
}
static __device__ __forceinline__ void unpack2(u64 v, float& lo, float& hi) {
    asm("mov.b64 {%0, %1}, %2;" : "=f"(lo), "=f"(hi) : "l"(v));
}
#define FFMA2(acc, a, b) \
    asm("fma.rn.f32x2 %0, %1, %2, %0;" : "+l"(acc) : "l"(a), "l"(b))

#define LDS_V2B64(d0, d1, addr) \
    asm volatile("ld.shared.v2.b64 {%0, %1}, [%2];" : "=l"(d0), "=l"(d1) : "r"(addr))

// ---------------------------------------------------------------------------
// Kernel 1: fused bilinear vert_align + bottleneck GEMM + bias + ReLU -> g_y
// (non-persistent: keeps L1 large for the scattered image reads)
// ---------------------------------------------------------------------------
__global__ void __launch_bounds__(512)
k_bottleneck(const float* __restrict__ x, const float* __restrict__ verts,
             const float* __restrict__ bw, const float* __restrict__ bb)
{
    extern __shared__ float sm[];
    float* As   = sm;                       // [BM][262]
    float* Ws   = As + BM * 262;            // [32][128]
    int*   sIdx = (int*)(Ws + 32 * 128);    // [BM][4]
    float* sW   = (float*)(sIdx + BM * 4);  // [BM][4]

    const int tid = threadIdx.x;
    const int v0  = blockIdx.x * BM;

    if (tid < BM) {
        int v = v0 + tid;
        float px = (verts[v * 3 + 0] + 1.0f) * 0.5f * (float)(HWD - 1);
        float py = (verts[v * 3 + 1] + 1.0f) * 0.5f * (float)(HWD - 1);
        float x0f = floorf(px), y0f = floorf(py);
        float wx = px - x0f, wy = py - y0f;
        int x0 = (int)x0f; x0 = x0 < 0 ? 0 : (x0 > HWD - 1 ? HWD - 1 : x0);
        int x1 = x0 + 1 > HWD - 1 ? HWD - 1 : x0 + 1;
        int y0 = (int)y0f; y0 = y0 < 0 ? 0 : (y0 > HWD - 1 ? HWD - 1 : y0);
        int y1 = y0 + 1 > HWD - 1 ? HWD - 1 : y0 + 1;
        sIdx[tid * 4 + 0] = y0 * HWD + x0;
        sIdx[tid * 4 + 1] = y0 * HWD + x1;
        sIdx[tid * 4 + 2] = y1 * HWD + x0;
        sIdx[tid * 4 + 3] = y1 * HWD + x1;
        sW[tid * 4 + 0] = (1.0f - wx) * (1.0f - wy);
        sW[tid * 4 + 1] = wx * (1.0f - wy);
        sW[tid * 4 + 2] = (1.0f - wx) * wy;
        sW[tid * 4 + 3] = wx * wy;
    }
    __syncthreads();

    // A tile: 2 threads per channel, 32 verts each
    {
        const int c  = tid & 255;
        const int mh = (tid >> 8) * 32;
        const float* im = x + c * (HWD * HWD);
        #pragma unroll 4
        for (int mm = 0; mm < 32; mm++) {
            int m = mh + mm;
            float val = sW[m * 4 + 0] * im[sIdx[m * 4 + 0]]
                      + sW[m * 4 + 1] * im[sIdx[m * 4 + 1]]
                      + sW[m * 4 + 2] * im[sIdx[m * 4 + 2]]
                      + sW[m * 4 + 3] * im[sIdx[m * 4 + 3]];
            As[m * 262 + c] = val;
        }
    }

    const int m0 = tid & 15;
    const int n0 = (tid >> 4) << 2;
    const unsigned ws_b = smem_u32(Ws) + n0 * 4;

    float4 bias = *(const float4*)(bb + n0);
    u64 acc[4][2];
    u64 b01 = pack2(bias.x, bias.y), b23 = pack2(bias.z, bias.w);
    #pragma unroll
    for (int i = 0; i < 4; i++) { acc[i][0] = b01; acc[i][1] = b23; }

    for (int kc = 0; kc < CIMG; kc += 32) {
        __syncthreads();
        #pragma unroll
        for (int t = 0; t < 2; t++)
            ((float4*)Ws)[t * 512 + tid] = ((const float4*)(bw + kc * HID))[t * 512 + tid];
        __syncthreads();
        #pragma unroll
        for (int kk = 0; kk < 32; kk++) {
            u64 w01, w23;
            LDS_V2B64(w01, w23, ws_b + (kk * HID) * 4);
            #pragma unroll
            for (int i = 0; i < 4; i++) {
                u64 a = pack_dup(As[(m0 + 16 * i) * 262 + kc + kk]);
                FFMA2(acc[i][0], a, w01);
                FFMA2(acc[i][1], a, w23);
            }
        }
    }
    #pragma unroll
    for (int i = 0; i < 4; i++) {
        int v = v0 + m0 + 16 * i;
        float f0, f1, f2, f3;
        unpack2(acc[i][0], f0, f1);
        unpack2(acc[i][1], f2, f3);
        *(float4*)(g_y + (size_t)v * HID + n0) =
            make_float4(fmaxf(f0, 0.f), fmaxf(f1, 0.f), fmaxf(f2, 0.f), fmaxf(f3, 0.f));
    }
}

// ---------------------------------------------------------------------------
// Kernel 2: persistent GCN layer GEMM pair. Both weight matrices live in SMEM
// for the whole kernel; the CTA loops over vertex tiles. No barriers in the
// 131-step k-loop.
//   A = [relu(g_y), verts];  g_y <- A@w0 + b0;  g_z <- A@w1 + b1
// ---------------------------------------------------------------------------
__global__ void __launch_bounds__(512)
k_layer(const float* __restrict__ verts,
        const float* __restrict__ w0, const float* __restrict__ b0,
        const float* __restrict__ w1, const float* __restrict__ b1)
{
    extern __shared__ float sm[];
    float* Ws0 = sm;                   // [131][128]
    float* Ws1 = Ws0 + DIN * HID;      // [131][128]
    float* As  = Ws1 + DIN * HID;      // [BM][134]  (134 % 32 == 6 -> conflict-free)

    const int tid = threadIdx.x;

    // load full weights once
    for (int idx = tid; idx < (DIN * HID) / 4; idx += 512) {
        ((float4*)Ws0)[idx] = ((const float4*)w0)[idx];
        ((float4*)Ws1)[idx] = ((const float4*)w1)[idx];
    }

    const int m0 = tid & 15;
    const int n0 = (tid >> 4) << 2;
    const unsigned ws0_b = smem_u32(Ws0) + n0 * 4;
    const unsigned ws1_b = smem_u32(Ws1) + n0 * 4;

    float4 by = *(const float4*)(b0 + n0);
    float4 bz = *(const float4*)(b1 + n0);
    const u64 y01 = pack2(by.x, by.y), y23 = pack2(by.z, by.w);
    const u64 z01 = pack2(bz.x, bz.y), z23 = pack2(bz.z, bz.w);

    for (int tile = blockIdx.x; tile < NTILES; tile += gridDim.x) {
        const int v0 = tile * BM;
        __syncthreads();   // previous tile's readers done (also orders weight load on 1st)

        // A tile: relu'd activations + vertex coords
        #pragma unroll
        for (int t = 0; t < 4; t++) {
            int idx = tid + t * 512;
            int m = idx >> 5, c4 = idx & 31;
            float4 f = *(const float4*)(g_y + (size_t)(v0 + m) * HID + c4 * 4);
            float* dst = As + m * 134 + c4 * 4;
            *(float2*)dst       = make_float2(fmaxf(f.x, 0.f), fmaxf(f.y, 0.f));
            *(float2*)(dst + 2) = make_float2(fmaxf(f.z, 0.f), fmaxf(f.w, 0.f));
        }
        if (tid < BM) {
            int v = v0 + tid;
            As[tid * 134 + 128] = verts[v * 3 + 0];
            As[tid * 134 + 129] = verts[v * 3 + 1];
            As[tid * 134 + 130] = verts[v * 3 + 2];
        }
        __syncthreads();

        u64 accY[4][2], accZ[4][2];
        #pragma unroll
        for (int i = 0; i < 4; i++) {
            accY[i][0] = y01; accY[i][1] = y23;
            accZ[i][0] = z01; accZ[i][1] = z23;
        }

        #pragma unroll 8
        for (int kk = 0; kk < 128; kk++) {
            u64 wy01, wy23, wz01, wz23;
            LDS_V2B64(wy01, wy23, ws0_b + (kk * HID) * 4);
            LDS_V2B64(wz01, wz23, ws1_b + (kk * HID) * 4);
            #pragma unroll
            for (int i = 0; i < 4; i++) {
                u64 a = pack_dup(As[(m0 + 16 * i) * 134 + kk]);
                FFMA2(accY[i][0], a, wy01);
                FFMA2(accY[i][1], a, wy23);
                FFMA2(accZ[i][0], a, wz01);
                FFMA2(accZ[i][1], a, wz23);
            }
        }
        #pragma unroll
        for (int kk = 128; kk < DIN; kk++) {
            u64 wy01, wy23, wz01, wz23;
            LDS_V2B64(wy01, wy23, ws0_b + (kk * HID) * 4);
            LDS_V2B64(wz01, wz23, ws1_b + (kk * HID) * 4);
            #pragma unroll
            for (int i = 0; i < 4; i++) {
                u64 a = pack_dup(As[(m0 + 16 * i) * 134 + kk]);
                FFMA2(accY[i][0], a, wy01);
                FFMA2(accY[i][1], a, wy23);
                FFMA2(accZ[i][0], a, wz01);
                FFMA2(accZ[i][1], a, wz23);
            }
        }
        #pragma unroll
        for (int i = 0; i < 4; i++) {
            int v = v0 + m0 + 16 * i;
            float f0, f1, f2, f3;
            unpack2(accY[i][0], f0, f1);
            unpack2(accY[i][1], f2, f3);
            *(float4*)(g_y + (size_t)v * HID + n0) = make_float4(f0, f1, f2, f3);
            unpack2(accZ[i][0], f0, f1);
            unpack2(accZ[i][1], f2, f3);
            *(float4*)(g_z + (size_t)v * HID + n0) = make_float4(f0, f1, f2, f3);
        }
    }
}

// ---------------------------------------------------------------------------
// CSR build kernels (run once per launch; adjacency is launch-constant)
// ---------------------------------------------------------------------------
__global__ void k_zero_deg() {
    g_deg[blockIdx.x * 1024 + threadIdx.x] = 0;
}
__global__ void k_count(const int* __restrict__ edges) {
    int e = blockIdx.x * 256 + threadIdx.x;
    int e0 = edges[2 * e], e1 = edges[2 * e + 1];
    atomicAdd(&g_deg[e0], 1);
    atomicAdd(&g_deg[e1], 1);
}
static __device__ __forceinline__ int warp_incl_scan(int v, int lane, unsigned mask, int width) {
    #pragma unroll
    for (int o = 1; o < width; o <<= 1) {
        int n = __shfl_up_sync(mask, v, o);
        if (lane >= o) v += n;
    }
    return v;
}
__global__ void k_scan1() {
    __shared__ int wsum[32];
    int tid = threadIdx.x;
    int i = blockIdx.x * 1024 + tid;
    int lane = tid & 31, wid = tid >> 5;
    int d = g_deg[i];
    int incl = warp_incl_scan(d, lane, 0xffffffffu, 32);
    if (lane == 31) wsum[wid] = incl;
    __syncthreads();
    if (wid == 0) {
        int s = wsum[lane];
        int si = warp_incl_scan(s, lane, 0xffffffffu, 32);
        wsum[lane] = si - s;   // exclusive
    }
    __syncthreads();
    int excl = wsum[wid] + incl - d;
    g_off[i] = excl;
    if (tid == 1023) g_bsum[blockIdx.x] = excl + d;
}
__global__ void k_scan2() {
    __shared__ int wsum[8];
    int tid = threadIdx.x;
    int lane = tid & 31, wid = tid >> 5;
    int v = g_bsum[tid];
    int incl = warp_incl_scan(v, lane, 0xffffffffu, 32);
    if (lane == 31) wsum[wid] = incl;
    __syncthreads();
    if (tid < 8) {
        int s = wsum[tid];
        int si = warp_incl_scan(s, tid, 0xffu, 8);
        wsum[tid] = si - s;
    }
    __syncthreads();
    g_bsum[tid] = wsum[wid] + incl - v;   // exclusive scan of block sums
}
__global__ void k_scan3() {
    int i = blockIdx.x * 1024 + threadIdx.x;
    int o = g_off[i] + g_bsum[blockIdx.x];
    g_off[i] = o;
    g_cur[i] = o;
}
__global__ void k_fill(const int* __restrict__ edges) {
    int e = blockIdx.x * 256 + threadIdx.x;
    int e0 = edges[2 * e], e1 = edges[2 * e + 1];
    int p = atomicAdd(&g_cur[e0], 1);
    g_adj[p] = e1;
    int q = atomicAdd(&g_cur[e1], 1);
    g_adj[q] = e0;
}

// ---------------------------------------------------------------------------
// Kernel 3: gather (replaces atomic scatter). One warp per vertex:
//   g_y[v] += sum over neighbors u of g_z[u]
// ---------------------------------------------------------------------------
__global__ void __launch_bounds__(256)
k_gather()
{
    int gt = blockIdx.x * blockDim.x + threadIdx.x;
    int v = gt >> 5;
    int lane = gt & 31;

    int start = g_off[v];
    int deg   = g_deg[v];
    float* yp = g_y + (size_t)v * HID + lane * 4;
    float4 acc = *(float4*)yp;
    const int* ap = g_adj + start;

    int j = 0;
    for (; j + 2 <= deg; j += 2) {
        int u0 = __ldg(ap + j);
        int u1 = __ldg(ap + j + 1);
        float4 a = *(const float4*)(g_z + (size_t)u0 * HID + lane * 4);
        float4 b = *(const float4*)(g_z + (size_t)u1 * HID + lane * 4);
        acc.x += a.x + b.x; acc.y += a.y + b.y;
        acc.z += a.z + b.z; acc.w += a.w + b.w;
    }
    if (j < deg) {
        int u0 = __ldg(ap + j);
        float4 a = *(const float4*)(g_z + (size_t)u0 * HID + lane * 4);
        acc.x += a.x; acc.y += a.y; acc.z += a.z; acc.w += a.w;
    }
    *(float4*)yp = acc;
}

// ---------------------------------------------------------------------------
// Kernel 4: final head. One warp per vertex.
// ---------------------------------------------------------------------------
__global__ void __launch_bounds__(256)
k_final(const float* __restrict__ verts, const float* __restrict__ ow,
        const float* __restrict__ ob, float* __restrict__ out)
{
    int gt = blockIdx.x * blockDim.x + threadIdx.x;
    int v = gt >> 5;
    int lane = gt & 31;
    if (v >= NV) return;

    float4 f = *(const float4*)(g_y + (size_t)v * HID + lane * 4);
    f.x = fmaxf(f.x, 0.0f); f.y = fmaxf(f.y, 0.0f);
    f.z = fmaxf(f.z, 0.0f); f.w = fmaxf(f.w, 0.0f);
    *(float4*)(out + (size_t)NV * 3 + (size_t)v * HID + lane * 4) = f;

    int k = lane * 4;
    float s0 = f.x * ow[k * 3 + 0] + f.y * ow[(k + 1) * 3 + 0]
             + f.z * ow[(k + 2) * 3 + 0] + f.w * ow[(k + 3) * 3 + 0];
    float s1 = f.x * ow[k * 3 + 1] + f.y * ow[(k + 1) * 3 + 1]
             + f.z * ow[(k + 2) * 3 + 1] + f.w * ow[(k + 3) * 3 + 1];
    float s2 = f.x * ow[k * 3 + 2] + f.y * ow[(k + 1) * 3 + 2]
             + f.z * ow[(k + 2) * 3 + 2] + f.w * ow[(k + 3) * 3 + 2];
    #pragma unroll
    for (int off = 16; off; off >>= 1) {
        s0 += __shfl_xor_sync(0xffffffffu, s0, off);
        s1 += __shfl_xor_sync(0xffffffffu, s1, off);
        s2 += __shfl_xor_sync(0xffffffffu, s2, off);
    }
    if (lane == 0) {
        float vx = verts[v * 3 + 0], vy = verts[v * 3 + 1], vz = verts[v * 3 + 2];
        s0 += vx * ow[384] + vy * ow[387] + vz * ow[390] + ob[0];
        s1 += vx * ow[385] + vy * ow[388] + vz * ow[391] + ob[1];
        s2 += vx * ow[386] + vy * ow[389] + vz * ow[392] + ob[2];
        out[v * 3 + 0] = vx + tanhf(s0);
        out[v * 3 + 1] = vy + tanhf(s1);
        out[v * 3 + 2] = vz + tanhf(s2);
    }
}

// ---------------------------------------------------------------------------
extern "C" void kernel_launch(void* const* d_in, const int* in_sizes, int n_in,
                              void* d_out, int out_size)
{
    const float* x     = (const float*)d_in[0];
    const float* verts = (const float*)d_in[1];
    const int*   edges = (const int*)d_in[2];
    const float* bw    = (const float*)d_in[3];
    const float* bb    = (const float*)d_in[4];
    const float* w0    = (const float*)d_in[5];
    const float* b0    = (const float*)d_in[6];
    const float* w1    = (const float*)d_in[7];
    const float* b1    = (const float*)d_in[8];
    const float* ow    = (const float*)d_in[9];
    const float* ob    = (const float*)d_in[10];
    float* out = (float*)d_out;

    int nsm = 148;
    cudaDeviceGetAttribute(&nsm, cudaDevAttrMultiProcessorCount, 0);

    const int SMEM_BN = (BM * 262 + 32 * HID) * 4 + BM * 4 * 4 * 2;     // ~86 KB
    const int SMEM_LY = (2 * DIN * HID + BM * 134) * 4;                 // ~164.5 KB
    cudaFuncSetAttribute(k_bottleneck, cudaFuncAttributeMaxDynamicSharedMemorySize, SMEM_BN);
    cudaFuncSetAttribute(k_layer,      cudaFuncAttributeMaxDynamicSharedMemorySize, SMEM_LY);

    // bottleneck GEMM
    k_bottleneck<<<NTILES, 512, SMEM_BN>>>(x, verts, bw, bb);

    // CSR build (adjacency is launch-constant; reused by all 3 layers)
    k_zero_deg<<<NV / 1024, 1024>>>();
    k_count<<<NE / 256, 256>>>(edges);
    k_scan1<<<256, 1024>>>();
    k_scan2<<<1, 256>>>();
    k_scan3<<<256, 1024>>>();
    k_fill<<<NE / 256, 256>>>(edges);

    const int gat_blocks = (NV * 32) / 256;    // 32768
    for (int i = 0; i < 3; i++) {
        k_layer<<<nsm, 512, SMEM_LY>>>(verts,
                                       w0 + (size_t)i * DIN * HID, b0 + (size_t)i * HID,
                                       w1 + (size_t)i * DIN * HID, b1 + (size_t)i * HID);
        k_gather<<<gat_blocks, 256>>>();
    }

    const int fin_blocks = (NV * 32) / 256;    // 32768
    k_final<<<fin_blocks, 256>>>(verts, ow, ob, out);
}

// round 9
// speedup vs baseline: 1.6396x; 1.1288x over previous
#include <cuda_runtime.h>
#include <cuda_bf16.h>
#include <math.h>

#define NV 262144
#define NE 786432
#define CIMG 256
#define HID 128
#define HWD 64
#define DIN 131
#define BM 64
#define NTILES (NV / BM)

// bf16-split MMA layout constants (K padded 131 -> 144 = 9 k16 blocks)
#define NKB 9
#define NR (NKB * 4)            // 36 (kb,t) rows
#define WSTRIDE 130             // uint4 units per r-row of weights (130%8==2 -> uniform banks)
#define ASTRIDE 37              // uint4 units per m-row of A (odd -> uniform banks)
#define WQ_MAT (NR * WSTRIDE)   // 4680 uint4 per weight matrix
#define AQ_OFF (2 * WQ_MAT)     // 9360
#define SMEM16_LY (AQ_OFF + BM * ASTRIDE)   // 11728 uint4 = 187,648 B

typedef unsigned long long u64;

// scratch (static device globals; no runtime allocation allowed)
__device__ float g_y[(size_t)NV * HID];   // y accumulator / current activations
__device__ float g_z[(size_t)NV * HID];   // z (message) features
// CSR scratch
__device__ int g_deg[NV];
__device__ int g_off[NV];
__device__ int g_cur[NV];
__device__ int g_adj[2 * NE];
__device__ int g_bsum[256];

static __device__ __forceinline__ unsigned smem_u32(const void* p) {
    return (unsigned)__cvta_generic_to_shared(p);
}
static __device__ __forceinline__ u64 pack2(float lo, float hi) {
    u64 r;
    asm("mov.b64 %0, {%1, %2};" : "=l"(r) : "f"(lo), "f"(hi));
    return r;
}
static __device__ __forceinline__ u64 pack_dup(float a) {
    u64 r;
    asm("mov.b64 %0, {%1, %1};" : "=l"(r) : "f"(a));
    return r;
}
static __device__ __forceinline__ void unpack2(u64 v, float& lo, float& hi) {
    asm("mov.b64 {%0, %1}, %2;" : "=f"(lo), "=f"(hi) : "l"(v));
}
#define FFMA2(acc, a, b) \
    asm("fma.rn.f32x2 %0, %1, %2, %0;" : "+l"(acc) : "l"(a), "l"(b))

#define LDS_V2B64(d0, d1, addr) \
    asm volatile("ld.shared.v2.b64 {%0, %1}, [%2];" : "=l"(d0), "=l"(d1) : "r"(addr))

// ---- bf16 split helpers -----------------------------------------------------
// x = hi + lo with hi = bf16_rn(x), lo = bf16_rn(x - hi). Packs two k-adjacent
// values into one .b32 (element k in the low half, k+1 in the high half).
static __device__ __forceinline__ void split2(float x0, float x1,
                                              unsigned& hi, unsigned& lo) {
    __nv_bfloat16 h0 = __float2bfloat16_rn(x0);
    __nv_bfloat16 h1 = __float2bfloat16_rn(x1);
    float r0 = x0 - __bfloat162float(h0);
    float r1 = x1 - __bfloat162float(h1);
    __nv_bfloat16 l0 = __float2bfloat16_rn(r0);
    __nv_bfloat16 l1 = __float2bfloat16_rn(r1);
    hi = (unsigned)__bfloat16_as_ushort(h0) | ((unsigned)__bfloat16_as_ushort(h1) << 16);
    lo = (unsigned)__bfloat16_as_ushort(l0) | ((unsigned)__bfloat16_as_ushort(l1) << 16);
}

static __device__ __forceinline__ void mma_bf16(float& c0, float& c1, float& c2, float& c3,
                                                unsigned a0, unsigned a1, unsigned a2, unsigned a3,
                                                unsigned b0, unsigned b1) {
    asm volatile("mma.sync.aligned.m16n8k16.row.col.f32.bf16.bf16.f32 "
                 "{%0,%1,%2,%3}, {%4,%5,%6,%7}, {%8,%9}, {%0,%1,%2,%3};"
                 : "+f"(c0), "+f"(c1), "+f"(c2), "+f"(c3)
                 : "r"(a0), "r"(a1), "r"(a2), "r"(a3), "r"(b0), "r"(b1));
}

// ---------------------------------------------------------------------------
// Kernel 1: fused bilinear vert_align + bottleneck GEMM + bias + ReLU -> g_y
// (unchanged this round; convert to MMA next round if k_layer conversion lands)
// ---------------------------------------------------------------------------
__global__ void __launch_bounds__(512)
k_bottleneck(const float* __restrict__ x, const float* __restrict__ verts,
             const float* __restrict__ bw, const float* __restrict__ bb)
{
    extern __shared__ float sm[];
    float* As   = sm;                       // [BM][262]
    float* Ws   = As + BM * 262;            // [32][128]
    int*   sIdx = (int*)(Ws + 32 * 128);    // [BM][4]
    float* sW   = (float*)(sIdx + BM * 4);  // [BM][4]

    const int tid = threadIdx.x;
    const int v0  = blockIdx.x * BM;

    if (tid < BM) {
        int v = v0 + tid;
        float px = (verts[v * 3 + 0] + 1.0f) * 0.5f * (float)(HWD - 1);
        float py = (verts[v * 3 + 1] + 1.0f) * 0.5f * (float)(HWD - 1);
        float x0f = floorf(px), y0f = floorf(py);
        float wx = px - x0f, wy = py - y0f;
        int x0 = (int)x0f; x0 = x0 < 0 ? 0 : (x0 > HWD - 1 ? HWD - 1 : x0);
        int x1 = x0 + 1 > HWD - 1 ? HWD - 1 : x0 + 1;
        int y0 = (int)y0f; y0 = y0 < 0 ? 0 : (y0 > HWD - 1 ? HWD - 1 : y0);
        int y1 = y0 + 1 > HWD - 1 ? HWD - 1 : y0 + 1;
        sIdx[tid * 4 + 0] = y0 * HWD + x0;
        sIdx[tid * 4 + 1] = y0 * HWD + x1;
        sIdx[tid * 4 + 2] = y1 * HWD + x0;
        sIdx[tid * 4 + 3] = y1 * HWD + x1;
        sW[tid * 4 + 0] = (1.0f - wx) * (1.0f - wy);
        sW[tid * 4 + 1] = wx * (1.0f - wy);
        sW[tid * 4 + 2] = (1.0f - wx) * wy;
        sW[tid * 4 + 3] = wx * wy;
    }
    __syncthreads();

    {
        const int c  = tid & 255;
        const int mh = (tid >> 8) * 32;
        const float* im = x + c * (HWD * HWD);
        #pragma unroll 4
        for (int mm = 0; mm < 32; mm++) {
            int m = mh + mm;
            float val = sW[m * 4 + 0] * im[sIdx[m * 4 + 0]]
                      + sW[m * 4 + 1] * im[sIdx[m * 4 + 1]]
                      + sW[m * 4 + 2] * im[sIdx[m * 4 + 2]]
                      + sW[m * 4 + 3] * im[sIdx[m * 4 + 3]];
            As[m * 262 + c] = val;
        }
    }

    const int m0 = tid & 15;
    const int n0 = (tid >> 4) << 2;
    const unsigned ws_b = smem_u32(Ws) + n0 * 4;

    float4 bias = *(const float4*)(bb + n0);
    u64 acc[4][2];
    u64 b01 = pack2(bias.x, bias.y), b23 = pack2(bias.z, bias.w);
    #pragma unroll
    for (int i = 0; i < 4; i++) { acc[i][0] = b01; acc[i][1] = b23; }

    for (int kc = 0; kc < CIMG; kc += 32) {
        __syncthreads();
        #pragma unroll
        for (int t = 0; t < 2; t++)
            ((float4*)Ws)[t * 512 + tid] = ((const float4*)(bw + kc * HID))[t * 512 + tid];
        __syncthreads();
        #pragma unroll
        for (int kk = 0; kk < 32; kk++) {
            u64 w01, w23;
            LDS_V2B64(w01, w23, ws_b + (kk * HID) * 4);
            #pragma unroll
            for (int i = 0; i < 4; i++) {
                u64 a = pack_dup(As[(m0 + 16 * i) * 262 + kc + kk]);
                FFMA2(acc[i][0], a, w01);
                FFMA2(acc[i][1], a, w23);
            }
        }
    }
    #pragma unroll
    for (int i = 0; i < 4; i++) {
        int v = v0 + m0 + 16 * i;
        float f0, f1, f2, f3;
        unpack2(acc[i][0], f0, f1);
        unpack2(acc[i][1], f2, f3);
        *(float4*)(g_y + (size_t)v * HID + n0) =
            make_float4(fmaxf(f0, 0.f), fmaxf(f1, 0.f), fmaxf(f2, 0.f), fmaxf(f3, 0.f));
    }
}

// ---------------------------------------------------------------------------
// Kernel 2: persistent GCN layer GEMM pair on TENSOR CORES.
// bf16 2-way split (hi+lo), D = Ahi*Bhi + Ahi*Blo + Alo*Bhi  (fp32 accum).
// Weights split/packed into SMEM once per CTA; A tile split per tile.
// 16 warps: warp w -> mb = w&3 (16 m-rows), q = w>>2 (32 n-cols, both mats).
//   g_y <- [relu(g_y),verts] @ w0 + b0 ;  g_z <- same @ w1 + b1
// ---------------------------------------------------------------------------
__global__ void __launch_bounds__(512)
k_layer(const float* __restrict__ verts,
        const float* __restrict__ w0, const float* __restrict__ b0,
        const float* __restrict__ w1, const float* __restrict__ b1)
{
    extern __shared__ uint4 sq[];

    const int tid  = threadIdx.x;
    const int lane = tid & 31;
    const int wrp  = tid >> 5;
    const int g    = lane >> 2;
    const int t    = lane & 3;
    const int mb   = wrp & 3;
    const int q    = wrp >> 2;

    // ---- split+pack both weight matrices into SMEM (once) ----
    // entry (mat, r=kb*4+t, n) = {hi(k0,k0+1), hi(k2,k2+1), lo(k0,k0+1), lo(k2,k2+1)}
    for (int idx = tid; idx < 2 * NR * 128; idx += 512) {
        int mat = idx / (NR * 128);
        int rem = idx - mat * (NR * 128);
        int r = rem >> 7, n = rem & 127;
        int kb = r >> 2, tt = r & 3;
        int k0 = kb * 16 + 2 * tt, k2 = k0 + 8;
        const float* W = mat ? w1 : w0;
        float f0 = (k0     < DIN) ? W[(size_t)k0 * HID + n]       : 0.f;
        float f1 = (k0 + 1 < DIN) ? W[(size_t)(k0 + 1) * HID + n] : 0.f;
        float f2 = (k2     < DIN) ? W[(size_t)k2 * HID + n]       : 0.f;
        float f3 = (k2 + 1 < DIN) ? W[(size_t)(k2 + 1) * HID + n] : 0.f;
        unsigned h01, l01, h23, l23;
        split2(f0, f1, h01, l01);
        split2(f2, f3, h23, l23);
        sq[mat * WQ_MAT + r * WSTRIDE + n] = make_uint4(h01, h23, l01, l23);
    }

    // per-combo bias (col = (q*4+j)*8 + 2t, +1)
    float biasv[2][4][2];
    #pragma unroll
    for (int j = 0; j < 4; j++) {
        int col = (q * 4 + j) * 8 + 2 * t;
        biasv[0][j][0] = b0[col]; biasv[0][j][1] = b0[col + 1];
        biasv[1][j][0] = b1[col]; biasv[1][j][1] = b1[col + 1];
    }

    for (int tile = blockIdx.x; tile < NTILES; tile += gridDim.x) {
        const int v0 = tile * BM;
        __syncthreads();   // prior tile readers done (+ weight split on first iter)

        // ---- build split A tile: [relu(g_y), verts, 0-pad] ----
        for (int idx = tid; idx < BM * NR; idx += 512) {
            int m = idx / NR;
            int r = idx - m * NR;
            int kb = r >> 2, tt = r & 3;
            int v = v0 + m;
            float f0, f1, f2, f3;
            if (r < 32) {            // activation region k < 128
                int k0 = kb * 16 + 2 * tt;
                const float* yp = g_y + (size_t)v * HID;
                float2 p0 = *(const float2*)(yp + k0);
                float2 p1 = *(const float2*)(yp + k0 + 8);
                f0 = fmaxf(p0.x, 0.f); f1 = fmaxf(p0.y, 0.f);
                f2 = fmaxf(p1.x, 0.f); f3 = fmaxf(p1.y, 0.f);
            } else {                 // k = 128..143: verts at 128,129,130, rest 0
                f0 = f1 = f2 = f3 = 0.f;
                if (tt == 0)      { f0 = verts[v * 3 + 0]; f1 = verts[v * 3 + 1]; }
                else if (tt == 1) { f0 = verts[v * 3 + 2]; }
            }
            unsigned h01, l01, h23, l23;
            split2(f0, f1, h01, l01);
            split2(f2, f3, h23, l23);
            sq[AQ_OFF + m * ASTRIDE + r] = make_uint4(h01, h23, l01, l23);
        }
        __syncthreads();

        // ---- MMA mainloop ----
        float acc[2][4][4];
        #pragma unroll
        for (int mt = 0; mt < 2; mt++)
            #pragma unroll
            for (int j = 0; j < 4; j++) {
                acc[mt][j][0] = biasv[mt][j][0];
                acc[mt][j][1] = biasv[mt][j][1];
                acc[mt][j][2] = biasv[mt][j][0];
                acc[mt][j][3] = biasv[mt][j][1];
            }

        const uint4* aqm  = sq + AQ_OFF + (mb * 16 + g) * ASTRIDE;
        const uint4* aqm8 = aqm + 8 * ASTRIDE;

        #pragma unroll
        for (int kb = 0; kb < NKB; kb++) {
            int r = kb * 4 + t;
            uint4 aA = aqm[r];    // a0hi, a2hi, a0lo, a2lo   (rows g)
            uint4 aB = aqm8[r];   // a1hi, a3hi, a1lo, a3lo   (rows g+8)
            const uint4* wrow = sq + r * WSTRIDE + q * 32 + g;
            #pragma unroll
            for (int mt = 0; mt < 2; mt++) {
                #pragma unroll
                for (int j = 0; j < 4; j++) {
                    uint4 wv = wrow[mt * WQ_MAT + j * 8];  // b0hi,b1hi,b0lo,b1lo
                    float* c = acc[mt][j];
                    mma_bf16(c[0], c[1], c[2], c[3],
                             aA.x, aB.x, aA.y, aB.y, wv.x, wv.y);   // hi*hi
                    mma_bf16(c[0], c[1], c[2], c[3],
                             aA.x, aB.x, aA.y, aB.y, wv.z, wv.w);   // hi*lo
                    mma_bf16(c[0], c[1], c[2], c[3],
                             aA.z, aB.z, aA.w, aB.w, wv.x, wv.y);   // lo*hi
                }
            }
        }

        // ---- epilogue: c0,c1 -> row g; c2,c3 -> row g+8 ----
        int row = v0 + mb * 16 + g;
        #pragma unroll
        for (int mt = 0; mt < 2; mt++) {
            float* base = mt ? g_z : g_y;
            #pragma unroll
            for (int j = 0; j < 4; j++) {
                int col = (q * 4 + j) * 8 + 2 * t;
                *(float2*)(base + (size_t)row * HID + col) =
                    make_float2(acc[mt][j][0], acc[mt][j][1]);
                *(float2*)(base + (size_t)(row + 8) * HID + col) =
                    make_float2(acc[mt][j][2], acc[mt][j][3]);
            }
        }
    }
}

// ---------------------------------------------------------------------------
// CSR build kernels (run once per launch; adjacency is launch-constant)
// ---------------------------------------------------------------------------
__global__ void k_zero_deg() {
    g_deg[blockIdx.x * 1024 + threadIdx.x] = 0;
}
__global__ void k_count(const int* __restrict__ edges) {
    int e = blockIdx.x * 256 + threadIdx.x;
    int e0 = edges[2 * e], e1 = edges[2 * e + 1];
    atomicAdd(&g_deg[e0], 1);
    atomicAdd(&g_deg[e1], 1);
}
static __device__ __forceinline__ int warp_incl_scan(int v, int lane, unsigned mask, int width) {
    #pragma unroll
    for (int o = 1; o < width; o <<= 1) {
        int n = __shfl_up_sync(mask, v, o);
        if (lane >= o) v += n;
    }
    return v;
}
__global__ void k_scan1() {
    __shared__ int wsum[32];
    int tid = threadIdx.x;
    int i = blockIdx.x * 1024 + tid;
    int lane = tid & 31, wid = tid >> 5;
    int d = g_deg[i];
    int incl = warp_incl_scan(d, lane, 0xffffffffu, 32);
    if (lane == 31) wsum[wid] = incl;
    __syncthreads();
    if (wid == 0) {
        int s = wsum[lane];
        int si = warp_incl_scan(s, lane, 0xffffffffu, 32);
        wsum[lane] = si - s;   // exclusive
    }
    __syncthreads();
    int excl = wsum[wid] + incl - d;
    g_off[i] = excl;
    if (tid == 1023) g_bsum[blockIdx.x] = excl + d;
}
__global__ void k_scan2() {
    __shared__ int wsum[8];
    int tid = threadIdx.x;
    int lane = tid & 31, wid = tid >> 5;
    int v = g_bsum[tid];
    int incl = warp_incl_scan(v, lane, 0xffffffffu, 32);
    if (lane == 31) wsum[wid] = incl;
    __syncthreads();
    if (tid < 8) {
        int s = wsum[tid];
        int si = warp_incl_scan(s, tid, 0xffu, 8);
        wsum[tid] = si - s;
    }
    __syncthreads();
    g_bsum[tid] = wsum[wid] + incl - v;   // exclusive scan of block sums
}
__global__ void k_scan3() {
    int i = blockIdx.x * 1024 + threadIdx.x;
    int o = g_off[i] + g_bsum[blockIdx.x];
    g_off[i] = o;
    g_cur[i] = o;
}
__global__ void k_fill(const int* __restrict__ edges) {
    int e = blockIdx.x * 256 + threadIdx.x;
    int e0 = edges[2 * e], e1 = edges[2 * e + 1];
    int p = atomicAdd(&g_cur[e0], 1);
    g_adj[p] = e1;
    int q = atomicAdd(&g_cur[e1], 1);
    g_adj[q] = e0;
}

// ---------------------------------------------------------------------------
// Kernel 3: gather. One warp per vertex: g_y[v] += sum over neighbors of g_z
// ---------------------------------------------------------------------------
__global__ void __launch_bounds__(256)
k_gather()
{
    int gt = blockIdx.x * blockDim.x + threadIdx.x;
    int v = gt >> 5;
    int lane = gt & 31;

    int start = g_off[v];
    int deg   = g_deg[v];
    float* yp = g_y + (size_t)v * HID + lane * 4;
    float4 acc = *(float4*)yp;
    const int* ap = g_adj + start;

    int j = 0;
    for (; j + 2 <= deg; j += 2) {
        int u0 = __ldg(ap + j);
        int u1 = __ldg(ap + j + 1);
        float4 a = *(const float4*)(g_z + (size_t)u0 * HID + lane * 4);
        float4 b = *(const float4*)(g_z + (size_t)u1 * HID + lane * 4);
        acc.x += a.x + b.x; acc.y += a.y + b.y;
        acc.z += a.z + b.z; acc.w += a.w + b.w;
    }
    if (j < deg) {
        int u0 = __ldg(ap + j);
        float4 a = *(const float4*)(g_z + (size_t)u0 * HID + lane * 4);
        acc.x += a.x; acc.y += a.y; acc.z += a.z; acc.w += a.w;
    }
    *(float4*)yp = acc;
}

// ---------------------------------------------------------------------------
// Kernel 4: final head. One warp per vertex.
// ---------------------------------------------------------------------------
__global__ void __launch_bounds__(256)
k_final(const float* __restrict__ verts, const float* __restrict__ ow,
        const float* __restrict__ ob, float* __restrict__ out)
{
    int gt = blockIdx.x * blockDim.x + threadIdx.x;
    int v = gt >> 5;
    int lane = gt & 31;
    if (v >= NV) return;

    float4 f = *(const float4*)(g_y + (size_t)v * HID + lane * 4);
    f.x = fmaxf(f.x, 0.0f); f.y = fmaxf(f.y, 0.0f);
    f.z = fmaxf(f.z, 0.0f); f.w = fmaxf(f.w, 0.0f);
    *(float4*)(out + (size_t)NV * 3 + (size_t)v * HID + lane * 4) = f;

    int k = lane * 4;
    float s0 = f.x * ow[k * 3 + 0] + f.y * ow[(k + 1) * 3 + 0]
             + f.z * ow[(k + 2) * 3 + 0] + f.w * ow[(k + 3) * 3 + 0];
    float s1 = f.x * ow[k * 3 + 1] + f.y * ow[(k + 1) * 3 + 1]
             + f.z * ow[(k + 2) * 3 + 1] + f.w * ow[(k + 3) * 3 + 1];
    float s2 = f.x * ow[k * 3 + 2] + f.y * ow[(k + 1) * 3 + 2]
             + f.z * ow[(k + 2) * 3 + 2] + f.w * ow[(k + 3) * 3 + 2];
    #pragma unroll
    for (int off = 16; off; off >>= 1) {
        s0 += __shfl_xor_sync(0xffffffffu, s0, off);
        s1 += __shfl_xor_sync(0xffffffffu, s1, off);
        s2 += __shfl_xor_sync(0xffffffffu, s2, off);
    }
    if (lane == 0) {
        float vx = verts[v * 3 + 0], vy = verts[v * 3 + 1], vz = verts[v * 3 + 2];
        s0 += vx * ow[384] + vy * ow[387] + vz * ow[390] + ob[0];
        s1 += vx * ow[385] + vy * ow[388] + vz * ow[391] + ob[1];
        s2 += vx * ow[386] + vy * ow[389] + vz * ow[392] + ob[2];
        out[v * 3 + 0] = vx + tanhf(s0);
        out[v * 3 + 1] = vy + tanhf(s1);
        out[v * 3 + 2] = vz + tanhf(s2);
    }
}

// ---------------------------------------------------------------------------
extern "C" void kernel_launch(void* const* d_in, const int* in_sizes, int n_in,
                              void* d_out, int out_size)
{
    const float* x     = (const float*)d_in[0];
    const float* verts = (const float*)d_in[1];
    const int*   edges = (const int*)d_in[2];
    const float* bw    = (const float*)d_in[3];
    const float* bb    = (const float*)d_in[4];
    const float* w0    = (const float*)d_in[5];
    const float* b0    = (const float*)d_in[6];
    const float* w1    = (const float*)d_in[7];
    const float* b1    = (const float*)d_in[8];
    const float* ow    = (const float*)d_in[9];
    const float* ob    = (const float*)d_in[10];
    float* out = (float*)d_out;

    int nsm = 148;
    cudaDeviceGetAttribute(&nsm, cudaDevAttrMultiProcessorCount, 0);

    const int SMEM_BN = (BM * 262 + 32 * HID) * 4 + BM * 4 * 4 * 2;   // ~86 KB
    const int SMEM_LY = SMEM16_LY * 16;                               // 187,648 B
    cudaFuncSetAttribute(k_bottleneck, cudaFuncAttributeMaxDynamicSharedMemorySize, SMEM_BN);
    cudaFuncSetAttribute(k_layer,      cudaFuncAttributeMaxDynamicSharedMemorySize, SMEM_LY);

    // bottleneck GEMM
    k_bottleneck<<<NTILES, 512, SMEM_BN>>>(x, verts, bw, bb);

    // CSR build (adjacency is launch-constant; reused by all 3 layers)
    k_zero_deg<<<NV / 1024, 1024>>>();
    k_count<<<NE / 256, 256>>>(edges);
    k_scan1<<<256, 1024>>>();
    k_scan2<<<1, 256>>>();
    k_scan3<<<256, 1024>>>();
    k_fill<<<NE / 256, 256>>>(edges);

    const int gat_blocks = (NV * 32) / 256;    // 32768
    for (int i = 0; i < 3; i++) {
        k_layer<<<nsm, 512, SMEM_LY>>>(verts,
                                       w0 + (size_t)i * DIN * HID, b0 + (size_t)i * HID,
                                       w1 + (size_t)i * DIN * HID, b1 + (size_t)i * HID);
        k_gather<<<gat_blocks, 256>>>();
    }

    const int fin_blocks = (NV * 32) / 256;    // 32768
    k_final<<<fin_blocks, 256>>>(verts, ow, ob, out);
}

// round 14
// speedup vs baseline: 2.8735x; 1.7526x over previous
#include <cuda_runtime.h>
#include <cuda_bf16.h>
#include <cuda_fp16.h>
#include <math.h>

#define NV 262144
#define NE 786432
#define CIMG 256
#define HID 128
#define HWD 64
#define NPIX (HWD * HWD)
#define DIN 131
#define BM 64
#define NTILES (NV / BM)

// ---- layer MMA layout (K padded 131 -> 144 = 9 k16 blocks) ----
#define NKB 9
#define NR (NKB * 4)            // 36 (kb,t) rows
#define WSTRIDE 130             // uint4 units per r-row of weights
#define ASTRIDE 37              // uint4 units per m-row of A
#define WQ_MAT (NR * WSTRIDE)   // 4680 uint4 per weight matrix
#define AQ_OFF (2 * WQ_MAT)     // 9360
#define SMEM16_LY (AQ_OFF + BM * ASTRIDE)     // 11728 uint4 = 187,648 B

// ---- bottleneck MMA layout (K = 256 = 16 k16 blocks) ----
#define NKB_BN 16
#define NR_BN (NKB_BN * 4)      // 64
#define WQ_BN (NR_BN * WSTRIDE) // 8320
#define ASTRIDE_BN 65
#define AQ_BN WQ_BN
#define SMEM16_BN (WQ_BN + BM * ASTRIDE_BN)   // 12480 uint4 = 199,680 B
#define SMEM_BN_BYTES (SMEM16_BN * 16 + BM * 4 * 8)   // + bilinear params

// scratch (static device globals; no runtime allocation allowed)
__device__ float  g_y[(size_t)NV * HID];      // y accumulator / activations
__device__ __half g_zh[(size_t)NV * HID];     // z (message) features, fp16
__device__ float  g_imgt[(size_t)NPIX * CIMG];// pixel-major image
// CSR scratch
__device__ int g_deg[NV];
__device__ int g_off[NV];
__device__ int g_cur[NV];
__device__ int g_adj[2 * NE];
__device__ int g_bsum[256];

// ---- bf16 split helpers -----------------------------------------------------
static __device__ __forceinline__ void split2(float x0, float x1,
                                              unsigned& hi, unsigned& lo) {
    __nv_bfloat16 h0 = __float2bfloat16_rn(x0);
    __nv_bfloat16 h1 = __float2bfloat16_rn(x1);
    float r0 = x0 - __bfloat162float(h0);
    float r1 = x1 - __bfloat162float(h1);
    __nv_bfloat16 l0 = __float2bfloat16_rn(r0);
    __nv_bfloat16 l1 = __float2bfloat16_rn(r1);
    hi = (unsigned)__bfloat16_as_ushort(h0) | ((unsigned)__bfloat16_as_ushort(h1) << 16);
    lo = (unsigned)__bfloat16_as_ushort(l0) | ((unsigned)__bfloat16_as_ushort(l1) << 16);
}

static __device__ __forceinline__ void mma_bf16(float& c0, float& c1, float& c2, float& c3,
                                                unsigned a0, unsigned a1, unsigned a2, unsigned a3,
                                                unsigned b0, unsigned b1) {
    asm volatile("mma.sync.aligned.m16n8k16.row.col.f32.bf16.bf16.f32 "
                 "{%0,%1,%2,%3}, {%4,%5,%6,%7}, {%8,%9}, {%0,%1,%2,%3};"
                 : "+f"(c0), "+f"(c1), "+f"(c2), "+f"(c3)
                 : "r"(a0), "r"(a1), "r"(a2), "r"(a3), "r"(b0), "r"(b1));
}

// ---------------------------------------------------------------------------
// Kernel 0: image transpose (C,H,W) -> (H*W, C), coalesced both ways.
// ---------------------------------------------------------------------------
__global__ void __launch_bounds__(256)
k_transpose(const float* __restrict__ x)
{
    __shared__ float t[32][33];
    int p0 = blockIdx.x * 32;    // pixel base
    int c0 = blockIdx.y * 32;    // channel base
    int tx = threadIdx.x & 31;
    int ty = threadIdx.x >> 5;   // 0..7
    #pragma unroll
    for (int i = 0; i < 4; i++)
        t[ty + i * 8][tx] = x[(size_t)(c0 + ty + i * 8) * NPIX + p0 + tx];
    __syncthreads();
    #pragma unroll
    for (int i = 0; i < 4; i++)
        g_imgt[(size_t)(p0 + ty + i * 8) * CIMG + c0 + tx] = t[tx][ty + i * 8];
}

// ---------------------------------------------------------------------------
// Kernel 1: persistent bottleneck on tensor cores.
//   g_y = relu( bilinear(img, verts) @ bw + bb )
// Weights (256x128) split-resident in SMEM; A tile built per tile from the
// pixel-major image with coalesced float2 loads.
// ---------------------------------------------------------------------------
__global__ void __launch_bounds__(512)
k_bottleneck(const float* __restrict__ verts,
             const float* __restrict__ bw, const float* __restrict__ bb)
{
    extern __shared__ uint4 sq[];
    int*   sIdx = (int*)(sq + SMEM16_BN);     // [BM][4]
    float* sW   = (float*)(sIdx + BM * 4);    // [BM][4]

    const int tid  = threadIdx.x;
    const int lane = tid & 31;
    const int wrp  = tid >> 5;
    const int g    = lane >> 2;
    const int t    = lane & 3;
    const int mb   = wrp & 3;
    const int q    = wrp >> 2;

    // split+pack weight matrix into SMEM (once)
    for (int idx = tid; idx < NR_BN * 128; idx += 512) {
        int r = idx >> 7, n = idx & 127;
        int kb = r >> 2, tt = r & 3;
        int k0 = kb * 16 + 2 * tt, k2 = k0 + 8;
        float f0 = bw[(size_t)k0 * HID + n];
        float f1 = bw[(size_t)(k0 + 1) * HID + n];
        float f2 = bw[(size_t)k2 * HID + n];
        float f3 = bw[(size_t)(k2 + 1) * HID + n];
        unsigned h01, l01, h23, l23;
        split2(f0, f1, h01, l01);
        split2(f2, f3, h23, l23);
        sq[r * WSTRIDE + n] = make_uint4(h01, h23, l01, l23);
    }

    float biasv[4][2];
    #pragma unroll
    for (int j = 0; j < 4; j++) {
        int col = (q * 4 + j) * 8 + 2 * t;
        biasv[j][0] = bb[col]; biasv[j][1] = bb[col + 1];
    }

    for (int tile = blockIdx.x; tile < NTILES; tile += gridDim.x) {
        const int v0 = tile * BM;
        __syncthreads();   // prior tile readers done (+ weight split on first iter)

        if (tid < BM) {
            int v = v0 + tid;
            float px = (verts[v * 3 + 0] + 1.0f) * 0.5f * (float)(HWD - 1);
            float py = (verts[v * 3 + 1] + 1.0f) * 0.5f * (float)(HWD - 1);
            float x0f = floorf(px), y0f = floorf(py);
            float wx = px - x0f, wy = py - y0f;
            int x0 = (int)x0f; x0 = x0 < 0 ? 0 : (x0 > HWD - 1 ? HWD - 1 : x0);
            int x1 = x0 + 1 > HWD - 1 ? HWD - 1 : x0 + 1;
            int y0 = (int)y0f; y0 = y0 < 0 ? 0 : (y0 > HWD - 1 ? HWD - 1 : y0);
            int y1 = y0 + 1 > HWD - 1 ? HWD - 1 : y0 + 1;
            sIdx[tid * 4 + 0] = y0 * HWD + x0;
            sIdx[tid * 4 + 1] = y0 * HWD + x1;
            sIdx[tid * 4 + 2] = y1 * HWD + x0;
            sIdx[tid * 4 + 3] = y1 * HWD + x1;
            sW[tid * 4 + 0] = (1.0f - wx) * (1.0f - wy);
            sW[tid * 4 + 1] = wx * (1.0f - wy);
            sW[tid * 4 + 2] = (1.0f - wx) * wy;
            sW[tid * 4 + 3] = wx * wy;
        }
        __syncthreads();

        // build split A tile from pixel-major image (coalesced float2 loads)
        #pragma unroll
        for (int tt8 = 0; tt8 < 8; tt8++) {
            int idx = tid + tt8 * 512;
            int m = idx >> 6, r = idx & 63;
            int kb = r >> 2, tt = r & 3;
            int k0 = kb * 16 + 2 * tt, k2 = k0 + 8;
            const float* t0 = g_imgt + (size_t)sIdx[m * 4 + 0] * CIMG;
            const float* t1 = g_imgt + (size_t)sIdx[m * 4 + 1] * CIMG;
            const float* t2 = g_imgt + (size_t)sIdx[m * 4 + 2] * CIMG;
            const float* t3 = g_imgt + (size_t)sIdx[m * 4 + 3] * CIMG;
            float w0v = sW[m * 4 + 0], w1v = sW[m * 4 + 1];
            float w2v = sW[m * 4 + 2], w3v = sW[m * 4 + 3];
            float2 pA0 = *(const float2*)(t0 + k0), pA2 = *(const float2*)(t0 + k2);
            float2 pB0 = *(const float2*)(t1 + k0), pB2 = *(const float2*)(t1 + k2);
            float2 pC0 = *(const float2*)(t2 + k0), pC2 = *(const float2*)(t2 + k2);
            float2 pD0 = *(const float2*)(t3 + k0), pD2 = *(const float2*)(t3 + k2);
            float f0 = w0v * pA0.x + w1v * pB0.x + w2v * pC0.x + w3v * pD0.x;
            float f1 = w0v * pA0.y + w1v * pB0.y + w2v * pC0.y + w3v * pD0.y;
            float f2 = w0v * pA2.x + w1v * pB2.x + w2v * pC2.x + w3v * pD2.x;
            float f3 = w0v * pA2.y + w1v * pB2.y + w2v * pC2.y + w3v * pD2.y;
            unsigned h01, l01, h23, l23;
            split2(f0, f1, h01, l01);
            split2(f2, f3, h23, l23);
            sq[AQ_BN + m * ASTRIDE_BN + r] = make_uint4(h01, h23, l01, l23);
        }
        __syncthreads();

        float acc[4][4];
        #pragma unroll
        for (int j = 0; j < 4; j++) {
            acc[j][0] = biasv[j][0]; acc[j][1] = biasv[j][1];
            acc[j][2] = biasv[j][0]; acc[j][3] = biasv[j][1];
        }

        const uint4* aqm  = sq + AQ_BN + (mb * 16 + g) * ASTRIDE_BN;
        const uint4* aqm8 = aqm + 8 * ASTRIDE_BN;

        #pragma unroll
        for (int kb = 0; kb < NKB_BN; kb++) {
            int r = kb * 4 + t;
            uint4 aA = aqm[r];
            uint4 aB = aqm8[r];
            const uint4* wrow = sq + r * WSTRIDE + q * 32 + g;
            #pragma unroll
            for (int j = 0; j < 4; j++) {
                uint4 wv = wrow[j * 8];
                float* c = acc[j];
                mma_bf16(c[0], c[1], c[2], c[3], aA.x, aB.x, aA.y, aB.y, wv.x, wv.y);
                mma_bf16(c[0], c[1], c[2], c[3], aA.x, aB.x, aA.y, aB.y, wv.z, wv.w);
                mma_bf16(c[0], c[1], c[2], c[3], aA.z, aB.z, aA.w, aB.w, wv.x, wv.y);
            }
        }

        int row = v0 + mb * 16 + g;
        #pragma unroll
        for (int j = 0; j < 4; j++) {
            int col = (q * 4 + j) * 8 + 2 * t;
            *(float2*)(g_y + (size_t)row * HID + col) =
                make_float2(fmaxf(acc[j][0], 0.f), fmaxf(acc[j][1], 0.f));
            *(float2*)(g_y + (size_t)(row + 8) * HID + col) =
                make_float2(fmaxf(acc[j][2], 0.f), fmaxf(acc[j][3], 0.f));
        }
    }
}

// ---------------------------------------------------------------------------
// Kernel 2: persistent GCN layer GEMM pair on tensor cores (bf16 split).
//   g_y <- [relu(g_y),verts] @ w0 + b0 (fp32);  g_zh <- same @ w1 + b1 (fp16)
// ---------------------------------------------------------------------------
__global__ void __launch_bounds__(512)
k_layer(const float* __restrict__ verts,
        const float* __restrict__ w0, const float* __restrict__ b0,
        const float* __restrict__ w1, const float* __restrict__ b1)
{
    extern __shared__ uint4 sq[];

    const int tid  = threadIdx.x;
    const int lane = tid & 31;
    const int wrp  = tid >> 5;
    const int g    = lane >> 2;
    const int t    = lane & 3;
    const int mb   = wrp & 3;
    const int q    = wrp >> 2;

    // split+pack both weight matrices into SMEM (once)
    for (int idx = tid; idx < 2 * NR * 128; idx += 512) {
        int mat = idx / (NR * 128);
        int rem = idx - mat * (NR * 128);
        int r = rem >> 7, n = rem & 127;
        int kb = r >> 2, tt = r & 3;
        int k0 = kb * 16 + 2 * tt, k2 = k0 + 8;
        const float* W = mat ? w1 : w0;
        float f0 = (k0     < DIN) ? W[(size_t)k0 * HID + n]       : 0.f;
        float f1 = (k0 + 1 < DIN) ? W[(size_t)(k0 + 1) * HID + n] : 0.f;
        float f2 = (k2     < DIN) ? W[(size_t)k2 * HID + n]       : 0.f;
        float f3 = (k2 + 1 < DIN) ? W[(size_t)(k2 + 1) * HID + n] : 0.f;
        unsigned h01, l01, h23, l23;
        split2(f0, f1, h01, l01);
        split2(f2, f3, h23, l23);
        sq[mat * WQ_MAT + r * WSTRIDE + n] = make_uint4(h01, h23, l01, l23);
    }

    float biasv[2][4][2];
    #pragma unroll
    for (int j = 0; j < 4; j++) {
        int col = (q * 4 + j) * 8 + 2 * t;
        biasv[0][j][0] = b0[col]; biasv[0][j][1] = b0[col + 1];
        biasv[1][j][0] = b1[col]; biasv[1][j][1] = b1[col + 1];
    }

    for (int tile = blockIdx.x; tile < NTILES; tile += gridDim.x) {
        const int v0 = tile * BM;
        __syncthreads();

        for (int idx = tid; idx < BM * NR; idx += 512) {
            int m = idx / NR;
            int r = idx - m * NR;
            int kb = r >> 2, tt = r & 3;
            int v = v0 + m;
            float f0, f1, f2, f3;
            if (r < 32) {
                int k0 = kb * 16 + 2 * tt;
                const float* yp = g_y + (size_t)v * HID;
                float2 p0 = *(const float2*)(yp + k0);
                float2 p1 = *(const float2*)(yp + k0 + 8);
                f0 = fmaxf(p0.x, 0.f); f1 = fmaxf(p0.y, 0.f);
                f2 = fmaxf(p1.x, 0.f); f3 = fmaxf(p1.y, 0.f);
            } else {
                f0 = f1 = f2 = f3 = 0.f;
                if (tt == 0)      { f0 = verts[v * 3 + 0]; f1 = verts[v * 3 + 1]; }
                else if (tt == 1) { f0 = verts[v * 3 + 2]; }
            }
            unsigned h01, l01, h23, l23;
            split2(f0, f1, h01, l01);
            split2(f2, f3, h23, l23);
            sq[AQ_OFF + m * ASTRIDE + r] = make_uint4(h01, h23, l01, l23);
        }
        __syncthreads();

        float acc[2][4][4];
        #pragma unroll
        for (int mt = 0; mt < 2; mt++)
            #pragma unroll
            for (int j = 0; j < 4; j++) {
                acc[mt][j][0] = biasv[mt][j][0];
                acc[mt][j][1] = biasv[mt][j][1];
                acc[mt][j][2] = biasv[mt][j][0];
                acc[mt][j][3] = biasv[mt][j][1];
            }

        const uint4* aqm  = sq + AQ_OFF + (mb * 16 + g) * ASTRIDE;
        const uint4* aqm8 = aqm + 8 * ASTRIDE;

        #pragma unroll
        for (int kb = 0; kb < NKB; kb++) {
            int r = kb * 4 + t;
            uint4 aA = aqm[r];
            uint4 aB = aqm8[r];
            const uint4* wrow = sq + r * WSTRIDE + q * 32 + g;
            #pragma unroll
            for (int mt = 0; mt < 2; mt++) {
                #pragma unroll
                for (int j = 0; j < 4; j++) {
                    uint4 wv = wrow[mt * WQ_MAT + j * 8];
                    float* c = acc[mt][j];
                    mma_bf16(c[0], c[1], c[2], c[3], aA.x, aB.x, aA.y, aB.y, wv.x, wv.y);
                    mma_bf16(c[0], c[1], c[2], c[3], aA.x, aB.x, aA.y, aB.y, wv.z, wv.w);
                    mma_bf16(c[0], c[1], c[2], c[3], aA.z, aB.z, aA.w, aB.w, wv.x, wv.y);
                }
            }
        }

        int row = v0 + mb * 16 + g;
        #pragma unroll
        for (int j = 0; j < 4; j++) {
            int col = (q * 4 + j) * 8 + 2 * t;
            *(float2*)(g_y + (size_t)row * HID + col) =
                make_float2(acc[0][j][0], acc[0][j][1]);
            *(float2*)(g_y + (size_t)(row + 8) * HID + col) =
                make_float2(acc[0][j][2], acc[0][j][3]);
            *(__half2*)(g_zh + (size_t)row * HID + col) =
                __floats2half2_rn(acc[1][j][0], acc[1][j][1]);
            *(__half2*)(g_zh + (size_t)(row + 8) * HID + col) =
                __floats2half2_rn(acc[1][j][2], acc[1][j][3]);
        }
    }
}

// ---------------------------------------------------------------------------
// CSR build kernels (run once per launch; adjacency is launch-constant)
// ---------------------------------------------------------------------------
__global__ void k_zero_deg() {
    g_deg[blockIdx.x * 1024 + threadIdx.x] = 0;
}
__global__ void k_count(const int* __restrict__ edges) {
    int e = blockIdx.x * 256 + threadIdx.x;
    int e0 = edges[2 * e], e1 = edges[2 * e + 1];
    atomicAdd(&g_deg[e0], 1);
    atomicAdd(&g_deg[e1], 1);
}
static __device__ __forceinline__ int warp_incl_scan(int v, int lane, unsigned mask, int width) {
    #pragma unroll
    for (int o = 1; o < width; o <<= 1) {
        int n = __shfl_up_sync(mask, v, o);
        if (lane >= o) v += n;
    }
    return v;
}
__global__ void k_scan1() {
    __shared__ int wsum[32];
    int tid = threadIdx.x;
    int i = blockIdx.x * 1024 + tid;
    int lane = tid & 31, wid = tid >> 5;
    int d = g_deg[i];
    int incl = warp_incl_scan(d, lane, 0xffffffffu, 32);
    if (lane == 31) wsum[wid] = incl;
    __syncthreads();
    if (wid == 0) {
        int s = wsum[lane];
        int si = warp_incl_scan(s, lane, 0xffffffffu, 32);
        wsum[lane] = si - s;
    }
    __syncthreads();
    int excl = wsum[wid] + incl - d;
    g_off[i] = excl;
    if (tid == 1023) g_bsum[blockIdx.x] = excl + d;
}
__global__ void k_scan2() {
    __shared__ int wsum[8];
    int tid = threadIdx.x;
    int lane = tid & 31, wid = tid >> 5;
    int v = g_bsum[tid];
    int incl = warp_incl_scan(v, lane, 0xffffffffu, 32);
    if (lane == 31) wsum[wid] = incl;
    __syncthreads();
    if (tid < 8) {
        int s = wsum[tid];
        int si = warp_incl_scan(s, tid, 0xffu, 8);
        wsum[tid] = si - s;
    }
    __syncthreads();
    g_bsum[tid] = wsum[wid] + incl - v;
}
__global__ void k_scan3() {
    int i = blockIdx.x * 1024 + threadIdx.x;
    int o = g_off[i] + g_bsum[blockIdx.x];
    g_off[i] = o;
    g_cur[i] = o;
}
__global__ void k_fill(const int* __restrict__ edges) {
    int e = blockIdx.x * 256 + threadIdx.x;
    int e0 = edges[2 * e], e1 = edges[2 * e + 1];
    int p = atomicAdd(&g_cur[e0], 1);
    g_adj[p] = e1;
    int q = atomicAdd(&g_cur[e1], 1);
    g_adj[q] = e0;
}

// ---------------------------------------------------------------------------
// Kernel 3: gather. One warp per vertex: g_y[v] += sum over neighbors of z.
// z rows are fp16 (half read traffic vs fp32).
// ---------------------------------------------------------------------------
__global__ void __launch_bounds__(256)
k_gather()
{
    int gt = blockIdx.x * blockDim.x + threadIdx.x;
    int v = gt >> 5;
    int lane = gt & 31;

    int start = g_off[v];
    int deg   = g_deg[v];
    float* yp = g_y + (size_t)v * HID + lane * 4;
    float4 acc = *(float4*)yp;
    const int* ap = g_adj + start;

    int j = 0;
    for (; j + 2 <= deg; j += 2) {
        int u0 = __ldg(ap + j);
        int u1 = __ldg(ap + j + 1);
        uint2 ra = __ldg((const uint2*)(g_zh + (size_t)u0 * HID + lane * 4));
        uint2 rb = __ldg((const uint2*)(g_zh + (size_t)u1 * HID + lane * 4));
        float2 a0 = __half22float2(*(__half2*)&ra.x);
        float2 a1 = __half22float2(*(__half2*)&ra.y);
        float2 b0 = __half22float2(*(__half2*)&rb.x);
        float2 b1 = __half22float2(*(__half2*)&rb.y);
        acc.x += a0.x + b0.x; acc.y += a0.y + b0.y;
        acc.z += a1.x + b1.x; acc.w += a1.y + b1.y;
    }
    if (j < deg) {
        int u0 = __ldg(ap + j);
        uint2 ra = __ldg((const uint2*)(g_zh + (size_t)u0 * HID + lane * 4));
        float2 a0 = __half22float2(*(__half2*)&ra.x);
        float2 a1 = __half22float2(*(__half2*)&ra.y);
        acc.x += a0.x; acc.y += a0.y; acc.z += a1.x; acc.w += a1.y;
    }
    *(float4*)yp = acc;
}

// ---------------------------------------------------------------------------
// Kernel 4: final head. One warp per vertex.
// ---------------------------------------------------------------------------
__global__ void __launch_bounds__(256)
k_final(const float* __restrict__ verts, const float* __restrict__ ow,
        const float* __restrict__ ob, float* __restrict__ out)
{
    int gt = blockIdx.x * blockDim.x + threadIdx.x;
    int v = gt >> 5;
    int lane = gt & 31;
    if (v >= NV) return;

    float4 f = *(const float4*)(g_y + (size_t)v * HID + lane * 4);
    f.x = fmaxf(f.x, 0.0f); f.y = fmaxf(f.y, 0.0f);
    f.z = fmaxf(f.z, 0.0f); f.w = fmaxf(f.w, 0.0f);
    *(float4*)(out + (size_t)NV * 3 + (size_t)v * HID + lane * 4) = f;

    int k = lane * 4;
    float s0 = f.x * ow[k * 3 + 0] + f.y * ow[(k + 1) * 3 + 0]
             + f.z * ow[(k + 2) * 3 + 0] + f.w * ow[(k + 3) * 3 + 0];
    float s1 = f.x * ow[k * 3 + 1] + f.y * ow[(k + 1) * 3 + 1]
             + f.z * ow[(k + 2) * 3 + 1] + f.w * ow[(k + 3) * 3 + 1];
    float s2 = f.x * ow[k * 3 + 2] + f.y * ow[(k + 1) * 3 + 2]
             + f.z * ow[(k + 2) * 3 + 2] + f.w * ow[(k + 3) * 3 + 2];
    #pragma unroll
    for (int off = 16; off; off >>= 1) {
        s0 += __shfl_xor_sync(0xffffffffu, s0, off);
        s1 += __shfl_xor_sync(0xffffffffu, s1, off);
        s2 += __shfl_xor_sync(0xffffffffu, s2, off);
    }
    if (lane == 0) {
        float vx = verts[v * 3 + 0], vy = verts[v * 3 + 1], vz = verts[v * 3 + 2];
        s0 += vx * ow[384] + vy * ow[387] + vz * ow[390] + ob[0];
        s1 += vx * ow[385] + vy * ow[388] + vz * ow[391] + ob[1];
        s2 += vx * ow[386] + vy * ow[389] + vz * ow[392] + ob[2];
        out[v * 3 + 0] = vx + tanhf(s0);
        out[v * 3 + 1] = vy + tanhf(s1);
        out[v * 3 + 2] = vz + tanhf(s2);
    }
}

// ---------------------------------------------------------------------------
extern "C" void kernel_launch(void* const* d_in, const int* in_sizes, int n_in,
                              void* d_out, int out_size)
{
    const float* x     = (const float*)d_in[0];
    const float* verts = (const float*)d_in[1];
    const int*   edges = (const int*)d_in[2];
    const float* bw    = (const float*)d_in[3];
    const float* bb    = (const float*)d_in[4];
    const float* w0    = (const float*)d_in[5];
    const float* b0    = (const float*)d_in[6];
    const float* w1    = (const float*)d_in[7];
    const float* b1    = (const float*)d_in[8];
    const float* ow    = (const float*)d_in[9];
    const float* ob    = (const float*)d_in[10];
    float* out = (float*)d_out;

    int nsm = 148;
    cudaDeviceGetAttribute(&nsm, cudaDevAttrMultiProcessorCount, 0);

    const int SMEM_BN = SMEM_BN_BYTES;       // ~201.7 KB
    const int SMEM_LY = SMEM16_LY * 16;      // 187,648 B
    cudaFuncSetAttribute(k_bottleneck, cudaFuncAttributeMaxDynamicSharedMemorySize, SMEM_BN);
    cudaFuncSetAttribute(k_layer,      cudaFuncAttributeMaxDynamicSharedMemorySize, SMEM_LY);

    // image transpose (C,H,W) -> (HW, C)
    k_transpose<<<dim3(NPIX / 32, CIMG / 32), 256>>>(x);

    // bottleneck GEMM (persistent, tensor cores)
    k_bottleneck<<<nsm, 512, SMEM_BN>>>(verts, bw, bb);

    // CSR build (adjacency is launch-constant; reused by all 3 layers)
    k_zero_deg<<<NV / 1024, 1024>>>();
    k_count<<<NE / 256, 256>>>(edges);
    k_scan1<<<256, 1024>>>();
    k_scan2<<<1, 256>>>();
    k_scan3<<<256, 1024>>>();
    k_fill<<<NE / 256, 256>>>(edges);

    const int gat_blocks = (NV * 32) / 256;    // 32768
    for (int i = 0; i < 3; i++) {
        k_layer<<<nsm, 512, SMEM_LY>>>(verts,
                                       w0 + (size_t)i * DIN * HID, b0 + (size_t)i * HID,
                                       w1 + (size_t)i * DIN * HID, b1 + (size_t)i * HID);
        k_gather<<<gat_blocks, 256>>>();
    }

    const int fin_blocks = (NV * 32) / 256;    // 32768
    k_final<<<fin_blocks, 256>>>(verts, ow, ob, out);
}

// round 15
// speedup vs baseline: 3.0360x; 1.0566x over previous
#include <cuda_runtime.h>
#include <cuda_bf16.h>
#include <cuda_fp16.h>
#include <math.h>

#define NV 262144
#define NE 786432
#define CIMG 256
#define HID 128
#define HWD 64
#define NPIX (HWD * HWD)
#define DIN 131
#define BM 64
#define NTILES (NV / BM)

// ---- layer MMA layout (K padded 131 -> 144 = 9 k16 blocks) ----
#define NKB 9
#define NR (NKB * 4)            // 36 (kb,t) rows
#define WSTRIDE 130             // uint4 units per r-row of weights
#define ASTRIDE 37              // uint4 units per m-row of A
#define WQ_MAT (NR * WSTRIDE)   // 4680 uint4 per weight matrix
#define AQ_OFF (2 * WQ_MAT)     // 9360
#define SMEM16_LY (AQ_OFF + BM * ASTRIDE)     // 11728 uint4 = 187,648 B

// ---- bottleneck MMA layout (K = 256 = 16 k16 blocks) ----
#define NKB_BN 16
#define NR_BN (NKB_BN * 4)      // 64
#define WQ_BN (NR_BN * WSTRIDE) // 8320
#define ASTRIDE_BN 65
#define AQ_BN WQ_BN
#define SMEM16_BN (WQ_BN + BM * ASTRIDE_BN)   // 12480 uint4 = 199,680 B
#define SMEM_BN_BYTES (SMEM16_BN * 16 + BM * 4 * 8)   // + bilinear params

// scratch (static device globals; no runtime allocation allowed)
__device__ float  g_y[(size_t)NV * HID];      // y accumulator / activations
__device__ __half g_zh[(size_t)NV * HID];     // z (message) features, fp16
__device__ float  g_imgt[(size_t)NPIX * CIMG];// pixel-major image
// CSR scratch
__device__ int g_deg[NV];
__device__ int g_off[NV];
__device__ int g_cur[NV];
__device__ int g_adj[2 * NE];
__device__ int g_bsum[256];

// ---- bf16 split helpers -----------------------------------------------------
static __device__ __forceinline__ void split2(float x0, float x1,
                                              unsigned& hi, unsigned& lo) {
    __nv_bfloat16 h0 = __float2bfloat16_rn(x0);
    __nv_bfloat16 h1 = __float2bfloat16_rn(x1);
    float r0 = x0 - __bfloat162float(h0);
    float r1 = x1 - __bfloat162float(h1);
    __nv_bfloat16 l0 = __float2bfloat16_rn(r0);
    __nv_bfloat16 l1 = __float2bfloat16_rn(r1);
    hi = (unsigned)__bfloat16_as_ushort(h0) | ((unsigned)__bfloat16_as_ushort(h1) << 16);
    lo = (unsigned)__bfloat16_as_ushort(l0) | ((unsigned)__bfloat16_as_ushort(l1) << 16);
}

static __device__ __forceinline__ void mma_bf16(float& c0, float& c1, float& c2, float& c3,
                                                unsigned a0, unsigned a1, unsigned a2, unsigned a3,
                                                unsigned b0, unsigned b1) {
    asm volatile("mma.sync.aligned.m16n8k16.row.col.f32.bf16.bf16.f32 "
                 "{%0,%1,%2,%3}, {%4,%5,%6,%7}, {%8,%9}, {%0,%1,%2,%3};"
                 : "+f"(c0), "+f"(c1), "+f"(c2), "+f"(c3)
                 : "r"(a0), "r"(a1), "r"(a2), "r"(a3), "r"(b0), "r"(b1));
}

// ---------------------------------------------------------------------------
// Kernel 0: image transpose (C,H,W) -> (H*W, C), coalesced both ways.
// ---------------------------------------------------------------------------
__global__ void __launch_bounds__(256)
k_transpose(const float* __restrict__ x)
{
    __shared__ float t[32][33];
    int p0 = blockIdx.x * 32;
    int c0 = blockIdx.y * 32;
    int tx = threadIdx.x & 31;
    int ty = threadIdx.x >> 5;
    #pragma unroll
    for (int i = 0; i < 4; i++)
        t[ty + i * 8][tx] = x[(size_t)(c0 + ty + i * 8) * NPIX + p0 + tx];
    __syncthreads();
    #pragma unroll
    for (int i = 0; i < 4; i++)
        g_imgt[(size_t)(p0 + ty + i * 8) * CIMG + c0 + tx] = t[tx][ty + i * 8];
}

// ---------------------------------------------------------------------------
// Kernel 1: persistent bottleneck on tensor cores.
// ---------------------------------------------------------------------------
__global__ void __launch_bounds__(512)
k_bottleneck(const float* __restrict__ verts,
             const float* __restrict__ bw, const float* __restrict__ bb)
{
    extern __shared__ uint4 sq[];
    int*   sIdx = (int*)(sq + SMEM16_BN);     // [BM][4]
    float* sW   = (float*)(sIdx + BM * 4);    // [BM][4]

    const int tid  = threadIdx.x;
    const int lane = tid & 31;
    const int wrp  = tid >> 5;
    const int g    = lane >> 2;
    const int t    = lane & 3;
    const int mb   = wrp & 3;
    const int q    = wrp >> 2;

    for (int idx = tid; idx < NR_BN * 128; idx += 512) {
        int r = idx >> 7, n = idx & 127;
        int kb = r >> 2, tt = r & 3;
        int k0 = kb * 16 + 2 * tt, k2 = k0 + 8;
        float f0 = bw[(size_t)k0 * HID + n];
        float f1 = bw[(size_t)(k0 + 1) * HID + n];
        float f2 = bw[(size_t)k2 * HID + n];
        float f3 = bw[(size_t)(k2 + 1) * HID + n];
        unsigned h01, l01, h23, l23;
        split2(f0, f1, h01, l01);
        split2(f2, f3, h23, l23);
        sq[r * WSTRIDE + n] = make_uint4(h01, h23, l01, l23);
    }

    float biasv[4][2];
    #pragma unroll
    for (int j = 0; j < 4; j++) {
        int col = (q * 4 + j) * 8 + 2 * t;
        biasv[j][0] = bb[col]; biasv[j][1] = bb[col + 1];
    }

    for (int tile = blockIdx.x; tile < NTILES; tile += gridDim.x) {
        const int v0 = tile * BM;
        __syncthreads();

        if (tid < BM) {
            int v = v0 + tid;
            float px = (verts[v * 3 + 0] + 1.0f) * 0.5f * (float)(HWD - 1);
            float py = (verts[v * 3 + 1] + 1.0f) * 0.5f * (float)(HWD - 1);
            float x0f = floorf(px), y0f = floorf(py);
            float wx = px - x0f, wy = py - y0f;
            int x0 = (int)x0f; x0 = x0 < 0 ? 0 : (x0 > HWD - 1 ? HWD - 1 : x0);
            int x1 = x0 + 1 > HWD - 1 ? HWD - 1 : x0 + 1;
            int y0 = (int)y0f; y0 = y0 < 0 ? 0 : (y0 > HWD - 1 ? HWD - 1 : y0);
            int y1 = y0 + 1 > HWD - 1 ? HWD - 1 : y0 + 1;
            sIdx[tid * 4 + 0] = y0 * HWD + x0;
            sIdx[tid * 4 + 1] = y0 * HWD + x1;
            sIdx[tid * 4 + 2] = y1 * HWD + x0;
            sIdx[tid * 4 + 3] = y1 * HWD + x1;
            sW[tid * 4 + 0] = (1.0f - wx) * (1.0f - wy);
            sW[tid * 4 + 1] = wx * (1.0f - wy);
            sW[tid * 4 + 2] = (1.0f - wx) * wy;
            sW[tid * 4 + 3] = wx * wy;
        }
        __syncthreads();

        #pragma unroll
        for (int tt8 = 0; tt8 < 8; tt8++) {
            int idx = tid + tt8 * 512;
            int m = idx >> 6, r = idx & 63;
            int kb = r >> 2, tt = r & 3;
            int k0 = kb * 16 + 2 * tt, k2 = k0 + 8;
            const float* t0 = g_imgt + (size_t)sIdx[m * 4 + 0] * CIMG;
            const float* t1 = g_imgt + (size_t)sIdx[m * 4 + 1] * CIMG;
            const float* t2 = g_imgt + (size_t)sIdx[m * 4 + 2] * CIMG;
            const float* t3 = g_imgt + (size_t)sIdx[m * 4 + 3] * CIMG;
            float w0v = sW[m * 4 + 0], w1v = sW[m * 4 + 1];
            float w2v = sW[m * 4 + 2], w3v = sW[m * 4 + 3];
            float2 pA0 = *(const float2*)(t0 + k0), pA2 = *(const float2*)(t0 + k2);
            float2 pB0 = *(const float2*)(t1 + k0), pB2 = *(const float2*)(t1 + k2);
            float2 pC0 = *(const float2*)(t2 + k0), pC2 = *(const float2*)(t2 + k2);
            float2 pD0 = *(const float2*)(t3 + k0), pD2 = *(const float2*)(t3 + k2);
            float f0 = w0v * pA0.x + w1v * pB0.x + w2v * pC0.x + w3v * pD0.x;
            float f1 = w0v * pA0.y + w1v * pB0.y + w2v * pC0.y + w3v * pD0.y;
            float f2 = w0v * pA2.x + w1v * pB2.x + w2v * pC2.x + w3v * pD2.x;
            float f3 = w0v * pA2.y + w1v * pB2.y + w2v * pC2.y + w3v * pD2.y;
            unsigned h01, l01, h23, l23;
            split2(f0, f1, h01, l01);
            split2(f2, f3, h23, l23);
            sq[AQ_BN + m * ASTRIDE_BN + r] = make_uint4(h01, h23, l01, l23);
        }
        __syncthreads();

        float acc[4][4];
        #pragma unroll
        for (int j = 0; j < 4; j++) {
            acc[j][0] = biasv[j][0]; acc[j][1] = biasv[j][1];
            acc[j][2] = biasv[j][0]; acc[j][3] = biasv[j][1];
        }

        const uint4* aqm  = sq + AQ_BN + (mb * 16 + g) * ASTRIDE_BN;
        const uint4* aqm8 = aqm + 8 * ASTRIDE_BN;

        #pragma unroll
        for (int kb = 0; kb < NKB_BN; kb++) {
            int r = kb * 4 + t;
            uint4 aA = aqm[r];
            uint4 aB = aqm8[r];
            const uint4* wrow = sq + r * WSTRIDE + q * 32 + g;
            #pragma unroll
            for (int j = 0; j < 4; j++) {
                uint4 wv = wrow[j * 8];
                float* c = acc[j];
                mma_bf16(c[0], c[1], c[2], c[3], aA.x, aB.x, aA.y, aB.y, wv.x, wv.y);
                mma_bf16(c[0], c[1], c[2], c[3], aA.x, aB.x, aA.y, aB.y, wv.z, wv.w);
                mma_bf16(c[0], c[1], c[2], c[3], aA.z, aB.z, aA.w, aB.w, wv.x, wv.y);
            }
        }

        int row = v0 + mb * 16 + g;
        #pragma unroll
        for (int j = 0; j < 4; j++) {
            int col = (q * 4 + j) * 8 + 2 * t;
            *(float2*)(g_y + (size_t)row * HID + col) =
                make_float2(fmaxf(acc[j][0], 0.f), fmaxf(acc[j][1], 0.f));
            *(float2*)(g_y + (size_t)(row + 8) * HID + col) =
                make_float2(fmaxf(acc[j][2], 0.f), fmaxf(acc[j][3], 0.f));
        }
    }
}

// ---------------------------------------------------------------------------
// Kernel 2: persistent GCN layer GEMM pair on tensor cores (bf16 split).
//   g_y <- [relu(g_y),verts] @ w0 + b0 (fp32);  g_zh <- same @ w1 + b1 (fp16)
// ---------------------------------------------------------------------------
__global__ void __launch_bounds__(512)
k_layer(const float* __restrict__ verts,
        const float* __restrict__ w0, const float* __restrict__ b0,
        const float* __restrict__ w1, const float* __restrict__ b1)
{
    extern __shared__ uint4 sq[];

    const int tid  = threadIdx.x;
    const int lane = tid & 31;
    const int wrp  = tid >> 5;
    const int g    = lane >> 2;
    const int t    = lane & 3;
    const int mb   = wrp & 3;
    const int q    = wrp >> 2;

    for (int idx = tid; idx < 2 * NR * 128; idx += 512) {
        int mat = idx / (NR * 128);
        int rem = idx - mat * (NR * 128);
        int r = rem >> 7, n = rem & 127;
        int kb = r >> 2, tt = r & 3;
        int k0 = kb * 16 + 2 * tt, k2 = k0 + 8;
        const float* W = mat ? w1 : w0;
        float f0 = (k0     < DIN) ? W[(size_t)k0 * HID + n]       : 0.f;
        float f1 = (k0 + 1 < DIN) ? W[(size_t)(k0 + 1) * HID + n] : 0.f;
        float f2 = (k2     < DIN) ? W[(size_t)k2 * HID + n]       : 0.f;
        float f3 = (k2 + 1 < DIN) ? W[(size_t)(k2 + 1) * HID + n] : 0.f;
        unsigned h01, l01, h23, l23;
        split2(f0, f1, h01, l01);
        split2(f2, f3, h23, l23);
        sq[mat * WQ_MAT + r * WSTRIDE + n] = make_uint4(h01, h23, l01, l23);
    }

    float biasv[2][4][2];
    #pragma unroll
    for (int j = 0; j < 4; j++) {
        int col = (q * 4 + j) * 8 + 2 * t;
        biasv[0][j][0] = b0[col]; biasv[0][j][1] = b0[col + 1];
        biasv[1][j][0] = b1[col]; biasv[1][j][1] = b1[col + 1];
    }

    for (int tile = blockIdx.x; tile < NTILES; tile += gridDim.x) {
        const int v0 = tile * BM;
        __syncthreads();

        for (int idx = tid; idx < BM * NR; idx += 512) {
            int m = idx / NR;
            int r = idx - m * NR;
            int kb = r >> 2, tt = r & 3;
            int v = v0 + m;
            float f0, f1, f2, f3;
            if (r < 32) {
                int k0 = kb * 16 + 2 * tt;
                const float* yp = g_y + (size_t)v * HID;
                float2 p0 = *(const float2*)(yp + k0);
                float2 p1 = *(const float2*)(yp + k0 + 8);
                f0 = fmaxf(p0.x, 0.f); f1 = fmaxf(p0.y, 0.f);
                f2 = fmaxf(p1.x, 0.f); f3 = fmaxf(p1.y, 0.f);
            } else {
                f0 = f1 = f2 = f3 = 0.f;
                if (tt == 0)      { f0 = verts[v * 3 + 0]; f1 = verts[v * 3 + 1]; }
                else if (tt == 1) { f0 = verts[v * 3 + 2]; }
            }
            unsigned h01, l01, h23, l23;
            split2(f0, f1, h01, l01);
            split2(f2, f3, h23, l23);
            sq[AQ_OFF + m * ASTRIDE + r] = make_uint4(h01, h23, l01, l23);
        }
        __syncthreads();

        float acc[2][4][4];
        #pragma unroll
        for (int mt = 0; mt < 2; mt++)
            #pragma unroll
            for (int j = 0; j < 4; j++) {
                acc[mt][j][0] = biasv[mt][j][0];
                acc[mt][j][1] = biasv[mt][j][1];
                acc[mt][j][2] = biasv[mt][j][0];
                acc[mt][j][3] = biasv[mt][j][1];
            }

        const uint4* aqm  = sq + AQ_OFF + (mb * 16 + g) * ASTRIDE;
        const uint4* aqm8 = aqm + 8 * ASTRIDE;

        #pragma unroll
        for (int kb = 0; kb < NKB; kb++) {
            int r = kb * 4 + t;
            uint4 aA = aqm[r];
            uint4 aB = aqm8[r];
            const uint4* wrow = sq + r * WSTRIDE + q * 32 + g;
            #pragma unroll
            for (int mt = 0; mt < 2; mt++) {
                #pragma unroll
                for (int j = 0; j < 4; j++) {
                    uint4 wv = wrow[mt * WQ_MAT + j * 8];
                    float* c = acc[mt][j];
                    mma_bf16(c[0], c[1], c[2], c[3], aA.x, aB.x, aA.y, aB.y, wv.x, wv.y);
                    mma_bf16(c[0], c[1], c[2], c[3], aA.x, aB.x, aA.y, aB.y, wv.z, wv.w);
                    mma_bf16(c[0], c[1], c[2], c[3], aA.z, aB.z, aA.w, aB.w, wv.x, wv.y);
                }
            }
        }

        int row = v0 + mb * 16 + g;
        #pragma unroll
        for (int j = 0; j < 4; j++) {
            int col = (q * 4 + j) * 8 + 2 * t;
            *(float2*)(g_y + (size_t)row * HID + col) =
                make_float2(acc[0][j][0], acc[0][j][1]);
            *(float2*)(g_y + (size_t)(row + 8) * HID + col) =
                make_float2(acc[0][j][2], acc[0][j][3]);
            *(__half2*)(g_zh + (size_t)row * HID + col) =
                __floats2half2_rn(acc[1][j][0], acc[1][j][1]);
            *(__half2*)(g_zh + (size_t)(row + 8) * HID + col) =
                __floats2half2_rn(acc[1][j][2], acc[1][j][3]);
        }
    }
}

// ---------------------------------------------------------------------------
// CSR build kernels (run once per launch; adjacency is launch-constant)
// ---------------------------------------------------------------------------
__global__ void k_zero_deg() {
    g_deg[blockIdx.x * 1024 + threadIdx.x] = 0;
}
__global__ void k_count(const int* __restrict__ edges) {
    int e = blockIdx.x * 256 + threadIdx.x;
    int e0 = edges[2 * e], e1 = edges[2 * e + 1];
    atomicAdd(&g_deg[e0], 1);
    atomicAdd(&g_deg[e1], 1);
}
static __device__ __forceinline__ int warp_incl_scan(int v, int lane, unsigned mask, int width) {
    #pragma unroll
    for (int o = 1; o < width; o <<= 1) {
        int n = __shfl_up_sync(mask, v, o);
        if (lane >= o) v += n;
    }
    return v;
}
__global__ void k_scan1() {
    __shared__ int wsum[32];
    int tid = threadIdx.x;
    int i = blockIdx.x * 1024 + tid;
    int lane = tid & 31, wid = tid >> 5;
    int d = g_deg[i];
    int incl = warp_incl_scan(d, lane, 0xffffffffu, 32);
    if (lane == 31) wsum[wid] = incl;
    __syncthreads();
    if (wid == 0) {
        int s = wsum[lane];
        int si = warp_incl_scan(s, lane, 0xffffffffu, 32);
        wsum[lane] = si - s;
    }
    __syncthreads();
    int excl = wsum[wid] + incl - d;
    g_off[i] = excl;
    if (tid == 1023) g_bsum[blockIdx.x] = excl + d;
}
__global__ void k_scan2() {
    __shared__ int wsum[8];
    int tid = threadIdx.x;
    int lane = tid & 31, wid = tid >> 5;
    int v = g_bsum[tid];
    int incl = warp_incl_scan(v, lane, 0xffffffffu, 32);
    if (lane == 31) wsum[wid] = incl;
    __syncthreads();
    if (tid < 8) {
        int s = wsum[tid];
        int si = warp_incl_scan(s, tid, 0xffu, 8);
        wsum[tid] = si - s;
    }
    __syncthreads();
    g_bsum[tid] = wsum[wid] + incl - v;
}
__global__ void k_scan3() {
    int i = blockIdx.x * 1024 + threadIdx.x;
    int o = g_off[i] + g_bsum[blockIdx.x];
    g_off[i] = o;
    g_cur[i] = o;
}
__global__ void k_fill(const int* __restrict__ edges) {
    int e = blockIdx.x * 256 + threadIdx.x;
    int e0 = edges[2 * e], e1 = edges[2 * e + 1];
    int p = atomicAdd(&g_cur[e0], 1);
    g_adj[p] = e1;
    int q = atomicAdd(&g_cur[e1], 1);
    g_adj[q] = e0;
}

// ---------------------------------------------------------------------------
// Neighbor-sum helper: acc += sum over neighbors of z (fp16 rows), MLP=4.
// ---------------------------------------------------------------------------
static __device__ __forceinline__ void nbr_sum(float4& acc, int v, int lane)
{
    int start = g_off[v];
    int deg   = g_deg[v];
    const int* ap = g_adj + start;
    int j = 0;
    for (; j + 4 <= deg; j += 4) {
        int u0 = __ldg(ap + j + 0);
        int u1 = __ldg(ap + j + 1);
        int u2 = __ldg(ap + j + 2);
        int u3 = __ldg(ap + j + 3);
        uint2 r0 = __ldg((const uint2*)(g_zh + (size_t)u0 * HID + lane * 4));
        uint2 r1 = __ldg((const uint2*)(g_zh + (size_t)u1 * HID + lane * 4));
        uint2 r2 = __ldg((const uint2*)(g_zh + (size_t)u2 * HID + lane * 4));
        uint2 r3 = __ldg((const uint2*)(g_zh + (size_t)u3 * HID + lane * 4));
        float2 a0 = __half22float2(*(__half2*)&r0.x), a1 = __half22float2(*(__half2*)&r0.y);
        float2 b0 = __half22float2(*(__half2*)&r1.x), b1 = __half22float2(*(__half2*)&r1.y);
        float2 c0 = __half22float2(*(__half2*)&r2.x), c1 = __half22float2(*(__half2*)&r2.y);
        float2 d0 = __half22float2(*(__half2*)&r3.x), d1 = __half22float2(*(__half2*)&r3.y);
        acc.x += (a0.x + b0.x) + (c0.x + d0.x);
        acc.y += (a0.y + b0.y) + (c0.y + d0.y);
        acc.z += (a1.x + b1.x) + (c1.x + d1.x);
        acc.w += (a1.y + b1.y) + (c1.y + d1.y);
    }
    for (; j < deg; j++) {
        int u0 = __ldg(ap + j);
        uint2 r0 = __ldg((const uint2*)(g_zh + (size_t)u0 * HID + lane * 4));
        float2 a0 = __half22float2(*(__half2*)&r0.x), a1 = __half22float2(*(__half2*)&r0.y);
        acc.x += a0.x; acc.y += a0.y; acc.z += a1.x; acc.w += a1.y;
    }
}

// ---------------------------------------------------------------------------
// Kernel 3a: gather (layers 0,1). One warp per vertex: g_y[v] += Σ z[nbr]
// ---------------------------------------------------------------------------
__global__ void __launch_bounds__(256)
k_gather()
{
    int gt = blockIdx.x * blockDim.x + threadIdx.x;
    int v = gt >> 5;
    int lane = gt & 31;
    float* yp = g_y + (size_t)v * HID + lane * 4;
    float4 acc = *(float4*)yp;
    nbr_sum(acc, v, lane);
    *(float4*)yp = acc;
}

// ---------------------------------------------------------------------------
// Kernel 3b: fused last gather + final head. One warp per vertex:
//   f = relu(g_y[v] + Σ z[nbr])  -> out[3V + v*128 ...]
//   deform = tanh([f, verts] @ ow + ob);  out[v*3...] = verts + deform
// ---------------------------------------------------------------------------
__global__ void __launch_bounds__(256)
k_gather_final(const float* __restrict__ verts, const float* __restrict__ ow,
               const float* __restrict__ ob, float* __restrict__ out)
{
    int gt = blockIdx.x * blockDim.x + threadIdx.x;
    int v = gt >> 5;
    int lane = gt & 31;

    float4 f = *(const float4*)(g_y + (size_t)v * HID + lane * 4);
    nbr_sum(f, v, lane);
    f.x = fmaxf(f.x, 0.0f); f.y = fmaxf(f.y, 0.0f);
    f.z = fmaxf(f.z, 0.0f); f.w = fmaxf(f.w, 0.0f);
    *(float4*)(out + (size_t)NV * 3 + (size_t)v * HID + lane * 4) = f;

    int k = lane * 4;
    float s0 = f.x * ow[k * 3 + 0] + f.y * ow[(k + 1) * 3 + 0]
             + f.z * ow[(k + 2) * 3 + 0] + f.w * ow[(k + 3) * 3 + 0];
    float s1 = f.x * ow[k * 3 + 1] + f.y * ow[(k + 1) * 3 + 1]
             + f.z * ow[(k + 2) * 3 + 1] + f.w * ow[(k + 3) * 3 + 1];
    float s2 = f.x * ow[k * 3 + 2] + f.y * ow[(k + 1) * 3 + 2]
             + f.z * ow[(k + 2) * 3 + 2] + f.w * ow[(k + 3) * 3 + 2];
    #pragma unroll
    for (int off = 16; off; off >>= 1) {
        s0 += __shfl_xor_sync(0xffffffffu, s0, off);
        s1 += __shfl_xor_sync(0xffffffffu, s1, off);
        s2 += __shfl_xor_sync(0xffffffffu, s2, off);
    }
    if (lane == 0) {
        float vx = verts[v * 3 + 0], vy = verts[v * 3 + 1], vz = verts[v * 3 + 2];
        s0 += vx * ow[384] + vy * ow[387] + vz * ow[390] + ob[0];
        s1 += vx * ow[385] + vy * ow[388] + vz * ow[391] + ob[1];
        s2 += vx * ow[386] + vy * ow[389] + vz * ow[392] + ob[2];
        out[v * 3 + 0] = vx + tanhf(s0);
        out[v * 3 + 1] = vy + tanhf(s1);
        out[v * 3 + 2] = vz + tanhf(s2);
    }
}

// ---------------------------------------------------------------------------
extern "C" void kernel_launch(void* const* d_in, const int* in_sizes, int n_in,
                              void* d_out, int out_size)
{
    const float* x     = (const float*)d_in[0];
    const float* verts = (const float*)d_in[1];
    const int*   edges = (const int*)d_in[2];
    const float* bw    = (const float*)d_in[3];
    const float* bb    = (const float*)d_in[4];
    const float* w0    = (const float*)d_in[5];
    const float* b0    = (const float*)d_in[6];
    const float* w1    = (const float*)d_in[7];
    const float* b1    = (const float*)d_in[8];
    const float* ow    = (const float*)d_in[9];
    const float* ob    = (const float*)d_in[10];
    float* out = (float*)d_out;

    int nsm = 148;
    cudaDeviceGetAttribute(&nsm, cudaDevAttrMultiProcessorCount, 0);

    const int SMEM_BN = SMEM_BN_BYTES;       // ~201.7 KB
    const int SMEM_LY = SMEM16_LY * 16;      // 187,648 B
    cudaFuncSetAttribute(k_bottleneck, cudaFuncAttributeMaxDynamicSharedMemorySize, SMEM_BN);
    cudaFuncSetAttribute(k_layer,      cudaFuncAttributeMaxDynamicSharedMemorySize, SMEM_LY);

    // image transpose (C,H,W) -> (HW, C)
    k_transpose<<<dim3(NPIX / 32, CIMG / 32), 256>>>(x);

    // bottleneck GEMM (persistent, tensor cores)
    k_bottleneck<<<nsm, 512, SMEM_BN>>>(verts, bw, bb);

    // CSR build (adjacency is launch-constant; reused by all 3 layers)
    k_zero_deg<<<NV / 1024, 1024>>>();
    k_count<<<NE / 256, 256>>>(edges);
    k_scan1<<<256, 1024>>>();
    k_scan2<<<1, 256>>>();
    k_scan3<<<256, 1024>>>();
    k_fill<<<NE / 256, 256>>>(edges);

    const int gat_blocks = (NV * 32) / 256;    // 32768
    for (int i = 0; i < 3; i++) {
        k_layer<<<nsm, 512, SMEM_LY>>>(verts,
                                       w0 + (size_t)i * DIN * HID, b0 + (size_t)i * HID,
                                       w1 + (size_t)i * DIN * HID, b1 + (size_t)i * HID);
        if (i < 2)
            k_gather<<<gat_blocks, 256>>>();
        else
            k_gather_final<<<gat_blocks, 256>>>(verts, ow, ob, out);
    }
}

// round 17
// speedup vs baseline: 3.2498x; 1.0704x over previous
#include <cuda_runtime.h>
#include <cuda_bf16.h>
#include <cuda_fp16.h>
#include <math.h>

#define NV 262144
#define NE 786432
#define CIMG 256
#define HID 128
#define HWD 64
#define NPIX (HWD * HWD)
#define DIN 131
#define BM 64
#define NTILES (NV / BM)

// ---- layer MMA layout (K padded 131 -> 144 = 9 k16 blocks) ----
#define NKB 9
#define NR (NKB * 4)            // 36 (kb,t) rows
#define WSTRIDE 130             // uint4 units per r-row of weights
#define ASTRIDE 37              // uint4 units per m-row of A
#define WQ_MAT (NR * WSTRIDE)   // 4680 uint4 per weight matrix
#define AQ_OFF (2 * WQ_MAT)     // 9360
#define ABUF (BM * ASTRIDE)     // 2368 uint4 per A buffer
#define SMEM16_LY (AQ_OFF + 2 * ABUF)   // 14096 uint4 = 225,536 B (double-buffered A)
#define NENT (BM * NR)          // 2304 A-tile entries

// ---- bottleneck MMA layout (K = 256 = 16 k16 blocks) ----
#define NKB_BN 16
#define NR_BN (NKB_BN * 4)      // 64
#define WQ_BN (NR_BN * WSTRIDE) // 8320
#define ASTRIDE_BN 65
#define AQ_BN WQ_BN
#define SMEM16_BN (WQ_BN + BM * ASTRIDE_BN)   // 12480 uint4 = 199,680 B
#define SMEM_BN_BYTES (SMEM16_BN * 16 + BM * 4 * 8)   // + bilinear params

// scratch (static device globals; no runtime allocation allowed)
__device__ float  g_y[(size_t)NV * HID];      // y accumulator / activations
__device__ __half g_zh[(size_t)NV * HID];     // z (message) features, fp16
__device__ float  g_imgt[(size_t)NPIX * CIMG];// pixel-major image
// CSR scratch
__device__ int g_deg[NV];
__device__ int g_off[NV];
__device__ int g_cur[NV];
__device__ int g_adj[2 * NE];
__device__ int g_bsum[256];

// ---- bf16 split helpers -----------------------------------------------------
static __device__ __forceinline__ void split2(float x0, float x1,
                                              unsigned& hi, unsigned& lo) {
    __nv_bfloat16 h0 = __float2bfloat16_rn(x0);
    __nv_bfloat16 h1 = __float2bfloat16_rn(x1);
    float r0 = x0 - __bfloat162float(h0);
    float r1 = x1 - __bfloat162float(h1);
    __nv_bfloat16 l0 = __float2bfloat16_rn(r0);
    __nv_bfloat16 l1 = __float2bfloat16_rn(r1);
    hi = (unsigned)__bfloat16_as_ushort(h0) | ((unsigned)__bfloat16_as_ushort(h1) << 16);
    lo = (unsigned)__bfloat16_as_ushort(l0) | ((unsigned)__bfloat16_as_ushort(l1) << 16);
}

static __device__ __forceinline__ void mma_bf16(float& c0, float& c1, float& c2, float& c3,
                                                unsigned a0, unsigned a1, unsigned a2, unsigned a3,
                                                unsigned b0, unsigned b1) {
    asm volatile("mma.sync.aligned.m16n8k16.row.col.f32.bf16.bf16.f32 "
                 "{%0,%1,%2,%3}, {%4,%5,%6,%7}, {%8,%9}, {%0,%1,%2,%3};"
                 : "+f"(c0), "+f"(c1), "+f"(c2), "+f"(c3)
                 : "r"(a0), "r"(a1), "r"(a2), "r"(a3), "r"(b0), "r"(b1));
}

// ---------------------------------------------------------------------------
// Kernel 0: image transpose (C,H,W) -> (H*W, C), coalesced both ways.
// ---------------------------------------------------------------------------
__global__ void __launch_bounds__(256)
k_transpose(const float* __restrict__ x)
{
    __shared__ float t[32][33];
    int p0 = blockIdx.x * 32;
    int c0 = blockIdx.y * 32;
    int tx = threadIdx.x & 31;
    int ty = threadIdx.x >> 5;
    #pragma unroll
    for (int i = 0; i < 4; i++)
        t[ty + i * 8][tx] = x[(size_t)(c0 + ty + i * 8) * NPIX + p0 + tx];
    __syncthreads();
    #pragma unroll
    for (int i = 0; i < 4; i++)
        g_imgt[(size_t)(p0 + ty + i * 8) * CIMG + c0 + tx] = t[tx][ty + i * 8];
}

// ---------------------------------------------------------------------------
// Kernel 1: persistent bottleneck on tensor cores (unchanged from round 15).
// ---------------------------------------------------------------------------
__global__ void __launch_bounds__(512)
k_bottleneck(const float* __restrict__ verts,
             const float* __restrict__ bw, const float* __restrict__ bb)
{
    extern __shared__ uint4 sq[];
    int*   sIdx = (int*)(sq + SMEM16_BN);     // [BM][4]
    float* sW   = (float*)(sIdx + BM * 4);    // [BM][4]

    const int tid  = threadIdx.x;
    const int lane = tid & 31;
    const int wrp  = tid >> 5;
    const int g    = lane >> 2;
    const int t    = lane & 3;
    const int mb   = wrp & 3;
    const int q    = wrp >> 2;

    for (int idx = tid; idx < NR_BN * 128; idx += 512) {
        int r = idx >> 7, n = idx & 127;
        int kb = r >> 2, tt = r & 3;
        int k0 = kb * 16 + 2 * tt, k2 = k0 + 8;
        float f0 = bw[(size_t)k0 * HID + n];
        float f1 = bw[(size_t)(k0 + 1) * HID + n];
        float f2 = bw[(size_t)k2 * HID + n];
        float f3 = bw[(size_t)(k2 + 1) * HID + n];
        unsigned h01, l01, h23, l23;
        split2(f0, f1, h01, l01);
        split2(f2, f3, h23, l23);
        sq[r * WSTRIDE + n] = make_uint4(h01, h23, l01, l23);
    }

    float biasv[4][2];
    #pragma unroll
    for (int j = 0; j < 4; j++) {
        int col = (q * 4 + j) * 8 + 2 * t;
        biasv[j][0] = bb[col]; biasv[j][1] = bb[col + 1];
    }

    for (int tile = blockIdx.x; tile < NTILES; tile += gridDim.x) {
        const int v0 = tile * BM;
        __syncthreads();

        if (tid < BM) {
            int v = v0 + tid;
            float px = (verts[v * 3 + 0] + 1.0f) * 0.5f * (float)(HWD - 1);
            float py = (verts[v * 3 + 1] + 1.0f) * 0.5f * (float)(HWD - 1);
            float x0f = floorf(px), y0f = floorf(py);
            float wx = px - x0f, wy = py - y0f;
            int x0 = (int)x0f; x0 = x0 < 0 ? 0 : (x0 > HWD - 1 ? HWD - 1 : x0);
            int x1 = x0 + 1 > HWD - 1 ? HWD - 1 : x0 + 1;
            int y0 = (int)y0f; y0 = y0 < 0 ? 0 : (y0 > HWD - 1 ? HWD - 1 : y0);
            int y1 = y0 + 1 > HWD - 1 ? HWD - 1 : y0 + 1;
            sIdx[tid * 4 + 0] = y0 * HWD + x0;
            sIdx[tid * 4 + 1] = y0 * HWD + x1;
            sIdx[tid * 4 + 2] = y1 * HWD + x0;
            sIdx[tid * 4 + 3] = y1 * HWD + x1;
            sW[tid * 4 + 0] = (1.0f - wx) * (1.0f - wy);
            sW[tid * 4 + 1] = wx * (1.0f - wy);
            sW[tid * 4 + 2] = (1.0f - wx) * wy;
            sW[tid * 4 + 3] = wx * wy;
        }
        __syncthreads();

        #pragma unroll
        for (int tt8 = 0; tt8 < 8; tt8++) {
            int idx = tid + tt8 * 512;
            int m = idx >> 6, r = idx & 63;
            int kb = r >> 2, tt = r & 3;
            int k0 = kb * 16 + 2 * tt, k2 = k0 + 8;
            const float* t0 = g_imgt + (size_t)sIdx[m * 4 + 0] * CIMG;
            const float* t1 = g_imgt + (size_t)sIdx[m * 4 + 1] * CIMG;
            const float* t2 = g_imgt + (size_t)sIdx[m * 4 + 2] * CIMG;
            const float* t3 = g_imgt + (size_t)sIdx[m * 4 + 3] * CIMG;
            float w0v = sW[m * 4 + 0], w1v = sW[m * 4 + 1];
            float w2v = sW[m * 4 + 2], w3v = sW[m * 4 + 3];
            float2 pA0 = *(const float2*)(t0 + k0), pA2 = *(const float2*)(t0 + k2);
            float2 pB0 = *(const float2*)(t1 + k0), pB2 = *(const float2*)(t1 + k2);
            float2 pC0 = *(const float2*)(t2 + k0), pC2 = *(const float2*)(t2 + k2);
            float2 pD0 = *(const float2*)(t3 + k0), pD2 = *(const float2*)(t3 + k2);
            float f0 = w0v * pA0.x + w1v * pB0.x + w2v * pC0.x + w3v * pD0.x;
            float f1 = w0v * pA0.y + w1v * pB0.y + w2v * pC0.y + w3v * pD0.y;
            float f2 = w0v * pA2.x + w1v * pB2.x + w2v * pC2.x + w3v * pD2.x;
            float f3 = w0v * pA2.y + w1v * pB2.y + w2v * pC2.y + w3v * pD2.y;
            unsigned h01, l01, h23, l23;
            split2(f0, f1, h01, l01);
            split2(f2, f3, h23, l23);
            sq[AQ_BN + m * ASTRIDE_BN + r] = make_uint4(h01, h23, l01, l23);
        }
        __syncthreads();

        float acc[4][4];
        #pragma unroll
        for (int j = 0; j < 4; j++) {
            acc[j][0] = biasv[j][0]; acc[j][1] = biasv[j][1];
            acc[j][2] = biasv[j][0]; acc[j][3] = biasv[j][1];
        }

        const uint4* aqm  = sq + AQ_BN + (mb * 16 + g) * ASTRIDE_BN;
        const uint4* aqm8 = aqm + 8 * ASTRIDE_BN;

        #pragma unroll
        for (int kb = 0; kb < NKB_BN; kb++) {
            int r = kb * 4 + t;
            uint4 aA = aqm[r];
            uint4 aB = aqm8[r];
            const uint4* wrow = sq + r * WSTRIDE + q * 32 + g;
            #pragma unroll
            for (int j = 0; j < 4; j++) {
                uint4 wv = wrow[j * 8];
                float* c = acc[j];
                mma_bf16(c[0], c[1], c[2], c[3], aA.x, aB.x, aA.y, aB.y, wv.x, wv.y);
                mma_bf16(c[0], c[1], c[2], c[3], aA.x, aB.x, aA.y, aB.y, wv.z, wv.w);
                mma_bf16(c[0], c[1], c[2], c[3], aA.z, aB.z, aA.w, aB.w, wv.x, wv.y);
            }
        }

        int row = v0 + mb * 16 + g;
        #pragma unroll
        for (int j = 0; j < 4; j++) {
            int col = (q * 4 + j) * 8 + 2 * t;
            *(float2*)(g_y + (size_t)row * HID + col) =
                make_float2(fmaxf(acc[j][0], 0.f), fmaxf(acc[j][1], 0.f));
            *(float2*)(g_y + (size_t)(row + 8) * HID + col) =
                make_float2(fmaxf(acc[j][2], 0.f), fmaxf(acc[j][3], 0.f));
        }
    }
}

// ---------------------------------------------------------------------------
// Kernel 2: persistent GCN layer GEMM pair on tensor cores (bf16 split),
// software-pipelined with a double-buffered A tile. FIXED: store_a takes the
// buffer INDEX and scales by ABUF internally (round-16 bug: index was used as
// a raw uint4 offset, leaving buffer 1 uninitialized -> NaN).
// ---------------------------------------------------------------------------
__global__ void __launch_bounds__(512)
k_layer(const float* __restrict__ verts,
        const float* __restrict__ w0, const float* __restrict__ b0,
        const float* __restrict__ w1, const float* __restrict__ b1)
{
    extern __shared__ uint4 sq[];

    const int tid  = threadIdx.x;
    const int lane = tid & 31;
    const int wrp  = tid >> 5;
    const int g    = lane >> 2;
    const int t    = lane & 3;
    const int mb   = wrp & 3;
    const int q    = wrp >> 2;

    // split+pack both weight matrices into SMEM (once)
    for (int idx = tid; idx < 2 * NR * 128; idx += 512) {
        int mat = idx / (NR * 128);
        int rem = idx - mat * (NR * 128);
        int r = rem >> 7, n = rem & 127;
        int kb = r >> 2, tt = r & 3;
        int k0 = kb * 16 + 2 * tt, k2 = k0 + 8;
        const float* W = mat ? w1 : w0;
        float f0 = (k0     < DIN) ? W[(size_t)k0 * HID + n]       : 0.f;
        float f1 = (k0 + 1 < DIN) ? W[(size_t)(k0 + 1) * HID + n] : 0.f;
        float f2 = (k2     < DIN) ? W[(size_t)k2 * HID + n]       : 0.f;
        float f3 = (k2 + 1 < DIN) ? W[(size_t)(k2 + 1) * HID + n] : 0.f;
        unsigned h01, l01, h23, l23;
        split2(f0, f1, h01, l01);
        split2(f2, f3, h23, l23);
        sq[mat * WQ_MAT + r * WSTRIDE + n] = make_uint4(h01, h23, l01, l23);
    }

    float biasv[2][4][2];
    #pragma unroll
    for (int j = 0; j < 4; j++) {
        int col = (q * 4 + j) * 8 + 2 * t;
        biasv[0][j][0] = b0[col]; biasv[0][j][1] = b0[col + 1];
        biasv[1][j][0] = b1[col]; biasv[1][j][1] = b1[col + 1];
    }

    // ---- tile-invariant A-build metadata (5 entries per thread) ----
    int e_m[5], e_k0[5], e_case[5], e_sts[5];
    #pragma unroll
    for (int p = 0; p < 5; p++) {
        int idx = tid + p * 512;
        bool valid = idx < NENT;
        int ic = valid ? idx : 0;
        int m = ic / NR, r = ic - m * NR;
        int kb = r >> 2, tt = r & 3;
        e_m[p]  = m;
        e_k0[p] = kb * 16 + 2 * tt;
        // case: 0 = activations, 1 = verts xy, 2 = verts z, 3 = zeros, -1 = invalid
        e_case[p] = !valid ? -1 : (r < 32 ? 0 : (tt == 0 ? 1 : (tt == 1 ? 2 : 3)));
        e_sts[p] = m * ASTRIDE + r;
    }

    float pf[5][4];

    // prefetch for a given tile base (issues global loads)
    auto prefetch = [&](int v0) {
        #pragma unroll
        for (int p = 0; p < 5; p++) {
            int cs = e_case[p];
            if (cs < 0) continue;
            int v = v0 + e_m[p];
            if (cs == 0) {
                const float* yp = g_y + (size_t)v * HID + e_k0[p];
                float2 p0 = *(const float2*)yp;
                float2 p1 = *(const float2*)(yp + 8);
                pf[p][0] = fmaxf(p0.x, 0.f); pf[p][1] = fmaxf(p0.y, 0.f);
                pf[p][2] = fmaxf(p1.x, 0.f); pf[p][3] = fmaxf(p1.y, 0.f);
            } else if (cs == 1) {
                pf[p][0] = verts[v * 3 + 0]; pf[p][1] = verts[v * 3 + 1];
                pf[p][2] = 0.f; pf[p][3] = 0.f;
            } else if (cs == 2) {
                pf[p][0] = verts[v * 3 + 2]; pf[p][1] = 0.f;
                pf[p][2] = 0.f; pf[p][3] = 0.f;
            } else {
                pf[p][0] = pf[p][1] = pf[p][2] = pf[p][3] = 0.f;
            }
        }
    };
    // split + store prefetched registers into A buffer `bufidx` (0 or 1)
    auto store_a = [&](int bufidx) {
        const int boff = AQ_OFF + bufidx * ABUF;
        #pragma unroll
        for (int p = 0; p < 5; p++) {
            if (e_case[p] < 0) continue;
            unsigned h01, l01, h23, l23;
            split2(pf[p][0], pf[p][1], h01, l01);
            split2(pf[p][2], pf[p][3], h23, l23);
            sq[boff + e_sts[p]] = make_uint4(h01, h23, l01, l23);
        }
    };

    // ---- pipelined tile loop ----
    int tile = blockIdx.x;
    if (tile < NTILES) {
        prefetch(tile * BM);
        store_a(0);
    }
    __syncthreads();
    int buf = 0;

    while (tile < NTILES) {
        const int v0 = tile * BM;
        const int next = tile + gridDim.x;
        if (next < NTILES) prefetch(next * BM);   // LDGs in flight during MMA

        float acc[2][4][4];
        #pragma unroll
        for (int mt = 0; mt < 2; mt++)
            #pragma unroll
            for (int j = 0; j < 4; j++) {
                acc[mt][j][0] = biasv[mt][j][0];
                acc[mt][j][1] = biasv[mt][j][1];
                acc[mt][j][2] = biasv[mt][j][0];
                acc[mt][j][3] = biasv[mt][j][1];
            }

        const uint4* aqm  = sq + AQ_OFF + buf * ABUF + (mb * 16 + g) * ASTRIDE;
        const uint4* aqm8 = aqm + 8 * ASTRIDE;

        #pragma unroll
        for (int kb = 0; kb < NKB; kb++) {
            int r = kb * 4 + t;
            uint4 aA = aqm[r];
            uint4 aB = aqm8[r];
            const uint4* wrow = sq + r * WSTRIDE + q * 32 + g;
            #pragma unroll
            for (int mt = 0; mt < 2; mt++) {
                #pragma unroll
                for (int j = 0; j < 4; j++) {
                    uint4 wv = wrow[mt * WQ_MAT + j * 8];
                    float* c = acc[mt][j];
                    mma_bf16(c[0], c[1], c[2], c[3], aA.x, aB.x, aA.y, aB.y, wv.x, wv.y);
                    mma_bf16(c[0], c[1], c[2], c[3], aA.x, aB.x, aA.y, aB.y, wv.z, wv.w);
                    mma_bf16(c[0], c[1], c[2], c[3], aA.z, aB.z, aA.w, aB.w, wv.x, wv.y);
                }
            }
        }

        // epilogue
        int row = v0 + mb * 16 + g;
        #pragma unroll
        for (int j = 0; j < 4; j++) {
            int col = (q * 4 + j) * 8 + 2 * t;
            *(float2*)(g_y + (size_t)row * HID + col) =
                make_float2(acc[0][j][0], acc[0][j][1]);
            *(float2*)(g_y + (size_t)(row + 8) * HID + col) =
                make_float2(acc[0][j][2], acc[0][j][3]);
            *(__half2*)(g_zh + (size_t)row * HID + col) =
                __floats2half2_rn(acc[1][j][0], acc[1][j][1]);
            *(__half2*)(g_zh + (size_t)(row + 8) * HID + col) =
                __floats2half2_rn(acc[1][j][2], acc[1][j][3]);
        }

        if (next < NTILES) store_a(buf ^ 1);
        __syncthreads();
        buf ^= 1;
        tile = next;
    }
}

// ---------------------------------------------------------------------------
// CSR build kernels (run once per launch; adjacency is launch-constant)
// ---------------------------------------------------------------------------
__global__ void k_zero_deg() {
    g_deg[blockIdx.x * 1024 + threadIdx.x] = 0;
}
__global__ void k_count(const int* __restrict__ edges) {
    int e = blockIdx.x * 256 + threadIdx.x;
    int e0 = edges[2 * e], e1 = edges[2 * e + 1];
    atomicAdd(&g_deg[e0], 1);
    atomicAdd(&g_deg[e1], 1);
}
static __device__ __forceinline__ int warp_incl_scan(int v, int lane, unsigned mask, int width) {
    #pragma unroll
    for (int o = 1; o < width; o <<= 1) {
        int n = __shfl_up_sync(mask, v, o);
        if (lane >= o) v += n;
    }
    return v;
}
__global__ void k_scan1() {
    __shared__ int wsum[32];
    int tid = threadIdx.x;
    int i = blockIdx.x * 1024 + tid;
    int lane = tid & 31, wid = tid >> 5;
    int d = g_deg[i];
    int incl = warp_incl_scan(d, lane, 0xffffffffu, 32);
    if (lane == 31) wsum[wid] = incl;
    __syncthreads();
    if (wid == 0) {
        int s = wsum[lane];
        int si = warp_incl_scan(s, lane, 0xffffffffu, 32);
        wsum[lane] = si - s;
    }
    __syncthreads();
    int excl = wsum[wid] + incl - d;
    g_off[i] = excl;
    if (tid == 1023) g_bsum[blockIdx.x] = excl + d;
}
__global__ void k_scan2() {
    __shared__ int wsum[8];
    int tid = threadIdx.x;
    int lane = tid & 31, wid = tid >> 5;
    int v = g_bsum[tid];
    int incl = warp_incl_scan(v, lane, 0xffffffffu, 32);
    if (lane == 31) wsum[wid] = incl;
    __syncthreads();
    if (tid < 8) {
        int s = wsum[tid];
        int si = warp_incl_scan(s, tid, 0xffu, 8);
        wsum[tid] = si - s;
    }
    __syncthreads();
    g_bsum[tid] = wsum[wid] + incl - v;
}
__global__ void k_scan3() {
    int i = blockIdx.x * 1024 + threadIdx.x;
    int o = g_off[i] + g_bsum[blockIdx.x];
    g_off[i] = o;
    g_cur[i] = o;
}
__global__ void k_fill(const int* __restrict__ edges) {
    int e = blockIdx.x * 256 + threadIdx.x;
    int e0 = edges[2 * e], e1 = edges[2 * e + 1];
    int p = atomicAdd(&g_cur[e0], 1);
    g_adj[p] = e1;
    int q = atomicAdd(&g_cur[e1], 1);
    g_adj[q] = e0;
}

// ---------------------------------------------------------------------------
// Neighbor-sum helper: acc += sum over neighbors of z (fp16 rows), MLP=4.
// ---------------------------------------------------------------------------
static __device__ __forceinline__ void nbr_sum(float4& acc, int v, int lane)
{
    int start = g_off[v];
    int deg   = g_deg[v];
    const int* ap = g_adj + start;
    int j = 0;
    for (; j + 4 <= deg; j += 4) {
        int u0 = __ldg(ap + j + 0);
        int u1 = __ldg(ap + j + 1);
        int u2 = __ldg(ap + j + 2);
        int u3 = __ldg(ap + j + 3);
        uint2 r0 = __ldg((const uint2*)(g_zh + (size_t)u0 * HID + lane * 4));
        uint2 r1 = __ldg((const uint2*)(g_zh + (size_t)u1 * HID + lane * 4));
        uint2 r2 = __ldg((const uint2*)(g_zh + (size_t)u2 * HID + lane * 4));
        uint2 r3 = __ldg((const uint2*)(g_zh + (size_t)u3 * HID + lane * 4));
        float2 a0 = __half22float2(*(__half2*)&r0.x), a1 = __half22float2(*(__half2*)&r0.y);
        float2 b0 = __half22float2(*(__half2*)&r1.x), b1 = __half22float2(*(__half2*)&r1.y);
        float2 c0 = __half22float2(*(__half2*)&r2.x), c1 = __half22float2(*(__half2*)&r2.y);
        float2 d0 = __half22float2(*(__half2*)&r3.x), d1 = __half22float2(*(__half2*)&r3.y);
        acc.x += (a0.x + b0.x) + (c0.x + d0.x);
        acc.y += (a0.y + b0.y) + (c0.y + d0.y);
        acc.z += (a1.x + b1.x) + (c1.x + d1.x);
        acc.w += (a1.y + b1.y) + (c1.y + d1.y);
    }
    for (; j < deg; j++) {
        int u0 = __ldg(ap + j);
        uint2 r0 = __ldg((const uint2*)(g_zh + (size_t)u0 * HID + lane * 4));
        float2 a0 = __half22float2(*(__half2*)&r0.x), a1 = __half22float2(*(__half2*)&r0.y);
        acc.x += a0.x; acc.y += a0.y; acc.z += a1.x; acc.w += a1.y;
    }
}

// ---------------------------------------------------------------------------
// Kernel 3a: gather (layers 0,1). One warp per vertex: g_y[v] += Σ z[nbr]
// ---------------------------------------------------------------------------
__global__ void __launch_bounds__(256)
k_gather()
{
    int gt = blockIdx.x * blockDim.x + threadIdx.x;
    int v = gt >> 5;
    int lane = gt & 31;
    float* yp = g_y + (size_t)v * HID + lane * 4;
    float4 acc = *(float4*)yp;
    nbr_sum(acc, v, lane);
    *(float4*)yp = acc;
}

// ---------------------------------------------------------------------------
// Kernel 3b: fused last gather + final head.
// ---------------------------------------------------------------------------
__global__ void __launch_bounds__(256)
k_gather_final(const float* __restrict__ verts, const float* __restrict__ ow,
               const float* __restrict__ ob, float* __restrict__ out)
{
    int gt = blockIdx.x * blockDim.x + threadIdx.x;
    int v = gt >> 5;
    int lane = gt & 31;

    float4 f = *(const float4*)(g_y + (size_t)v * HID + lane * 4);
    nbr_sum(f, v, lane);
    f.x = fmaxf(f.x, 0.0f); f.y = fmaxf(f.y, 0.0f);
    f.z = fmaxf(f.z, 0.0f); f.w = fmaxf(f.w, 0.0f);
    *(float4*)(out + (size_t)NV * 3 + (size_t)v * HID + lane * 4) = f;

    int k = lane * 4;
    float s0 = f.x * ow[k * 3 + 0] + f.y * ow[(k + 1) * 3 + 0]
             + f.z * ow[(k + 2) * 3 + 0] + f.w * ow[(k + 3) * 3 + 0];
    float s1 = f.x * ow[k * 3 + 1] + f.y * ow[(k + 1) * 3 + 1]
             + f.z * ow[(k + 2) * 3 + 1] + f.w * ow[(k + 3) * 3 + 1];
    float s2 = f.x * ow[k * 3 + 2] + f.y * ow[(k + 1) * 3 + 2]
             + f.z * ow[(k + 2) * 3 + 2] + f.w * ow[(k + 3) * 3 + 2];
    #pragma unroll
    for (int off = 16; off; off >>= 1) {
        s0 += __shfl_xor_sync(0xffffffffu, s0, off);
        s1 += __shfl_xor_sync(0xffffffffu, s1, off);
        s2 += __shfl_xor_sync(0xffffffffu, s2, off);
    }
    if (lane == 0) {
        float vx = verts[v * 3 + 0], vy = verts[v * 3 + 1], vz = verts[v * 3 + 2];
        s0 += vx * ow[384] + vy * ow[387] + vz * ow[390] + ob[0];
        s1 += vx * ow[385] + vy * ow[388] + vz * ow[391] + ob[1];
        s2 += vx * ow[386] + vy * ow[389] + vz * ow[392] + ob[2];
        out[v * 3 + 0] = vx + tanhf(s0);
        out[v * 3 + 1] = vy + tanhf(s1);
        out[v * 3 + 2] = vz + tanhf(s2);
    }
}

// ---------------------------------------------------------------------------
extern "C" void kernel_launch(void* const* d_in, const int* in_sizes, int n_in,
                              void* d_out, int out_size)
{
    const float* x     = (const float*)d_in[0];
    const float* verts = (const float*)d_in[1];
    const int*   edges = (const int*)d_in[2];
    const float* bw    = (const float*)d_in[3];
    const float* bb    = (const float*)d_in[4];
    const float* w0    = (const float*)d_in[5];
    const float* b0    = (const float*)d_in[6];
    const float* w1    = (const float*)d_in[7];
    const float* b1    = (const float*)d_in[8];
    const float* ow    = (const float*)d_in[9];
    const float* ob    = (const float*)d_in[10];
    float* out = (float*)d_out;

    int nsm = 148;
    cudaDeviceGetAttribute(&nsm, cudaDevAttrMultiProcessorCount, 0);

    const int SMEM_BN = SMEM_BN_BYTES;       // ~201.7 KB
    const int SMEM_LY = SMEM16_LY * 16;      // 225,536 B (double-buffered A)
    cudaFuncSetAttribute(k_bottleneck, cudaFuncAttributeMaxDynamicSharedMemorySize, SMEM_BN);
    cudaFuncSetAttribute(k_layer,      cudaFuncAttributeMaxDynamicSharedMemorySize, SMEM_LY);

    // image transpose (C,H,W) -> (HW, C)
    k_transpose<<<dim3(NPIX / 32, CIMG / 32), 256>>>(x);

    // bottleneck GEMM (persistent, tensor cores)
    k_bottleneck<<<nsm, 512, SMEM_BN>>>(verts, bw, bb);

    // CSR build (adjacency is launch-constant; reused by all 3 layers)
    k_zero_deg<<<NV / 1024, 1024>>>();
    k_count<<<NE / 256, 256>>>(edges);
    k_scan1<<<256, 1024>>>();
    k_scan2<<<1, 256>>>();
    k_scan3<<<256, 1024>>>();
    k_fill<<<NE / 256, 256>>>(edges);

    const int gat_blocks = (NV * 32) / 256;    // 32768
    for (int i = 0; i < 3; i++) {
        k_layer<<<nsm, 512, SMEM_LY>>>(verts,
                                       w0 + (size_t)i * DIN * HID, b0 + (size_t)i * HID,
                                       w1 + (size_t)i * DIN * HID, b1 + (size_t)i * HID);
        if (i < 2)
            k_gather<<<gat_blocks, 256>>>();
        else
            k_gather_final<<<gat_blocks, 256>>>(verts, ow, ob, out);
    }
}